// round 1
// baseline (speedup 1.0000x reference)
#include <cuda_runtime.h>
#include <math.h>

#define BB   2
#define TT   2048
#define DD   2048
#define HH   16
#define HDIM 128
#define MROWS (BB*TT)   // 4096

// Scratch (device globals: allocation-free per harness rules)
__device__ float g_Q[(size_t)BB*HH*TT*HDIM];
__device__ float g_K[(size_t)BB*HH*TT*HDIM];
__device__ float g_V[(size_t)BB*HH*TT*HDIM];
__device__ float g_O[(size_t)MROWS*DD];
__device__ float g_c[DD];

// ---------------------------------------------------------------------------
// c[d] = 2 * sum_{j<4} v_embed[j][d]   (top_k with k == NVK selects everything)
// ---------------------------------------------------------------------------
__global__ void compute_c_kernel(const float* __restrict__ v_embed) {
    int d = blockIdx.x * 256 + threadIdx.x;
    if (d < DD)
        g_c[d] = 2.0f * (v_embed[d] + v_embed[DD + d] + v_embed[2*DD + d] + v_embed[3*DD + d]);
}

// ---------------------------------------------------------------------------
// V[b,h,t,hd] = x[b,t,h*128+hd] * c[h*128+hd]
// ---------------------------------------------------------------------------
__global__ void compute_v_kernel(const float* __restrict__ x) {
    int idx  = blockIdx.x * 256 + threadIdx.x;      // over B*T*D
    int dcol = idx & (DD - 1);
    int bt   = idx >> 11;                           // DD = 2048
    int b    = bt >> 11;                            // TT = 2048
    int t    = bt & (TT - 1);
    int h    = dcol >> 7;
    int hd   = dcol & 127;
    g_V[((size_t)(b*HH + h)*TT + t)*HDIM + hd] = x[idx] * g_c[dcol];
}

// ---------------------------------------------------------------------------
// NT SGEMM: C[M=4096,N=2048] = A[M,K=2048] * B[N,K]^T + bias[N]
// 128x128x16 tiles, 256 threads, 8x8 per thread.
// MODE 0: scatter to per-head layout g[b,h,t,hd]; MODE 1: row-major [M][N]
// ---------------------------------------------------------------------------
template<int MODE>
__global__ void __launch_bounds__(256, 2) gemm_nt_kernel(
    const float* __restrict__ A, const float* __restrict__ Bm,
    const float* __restrict__ bias, float* __restrict__ C)
{
    __shared__ __align__(16) float As[16][132];
    __shared__ __align__(16) float Bs[16][132];
    const int K = DD;

    int tid = threadIdx.x;
    int tx  = tid & 15;
    int ty  = tid >> 4;
    int row0 = blockIdx.y * 128;
    int col0 = blockIdx.x * 128;

    int lr = tid >> 2;            // 0..63
    int lk = (tid & 3) * 4;       // 0,4,8,12

    const float* Ap = A  + (size_t)(row0 + lr) * K + lk;
    const float* Bp = Bm + (size_t)(col0 + lr) * K + lk;

    float acc[8][8];
    #pragma unroll
    for (int i = 0; i < 8; i++)
        #pragma unroll
        for (int j = 0; j < 8; j++) acc[i][j] = 0.0f;

    for (int kb = 0; kb < K; kb += 16) {
        float4 a0 = *(const float4*)Ap;
        float4 a1 = *(const float4*)(Ap + (size_t)64 * K);
        float4 b0 = *(const float4*)Bp;
        float4 b1 = *(const float4*)(Bp + (size_t)64 * K);
        __syncthreads();
        As[lk+0][lr]    = a0.x; As[lk+1][lr]    = a0.y; As[lk+2][lr]    = a0.z; As[lk+3][lr]    = a0.w;
        As[lk+0][lr+64] = a1.x; As[lk+1][lr+64] = a1.y; As[lk+2][lr+64] = a1.z; As[lk+3][lr+64] = a1.w;
        Bs[lk+0][lr]    = b0.x; Bs[lk+1][lr]    = b0.y; Bs[lk+2][lr]    = b0.z; Bs[lk+3][lr]    = b0.w;
        Bs[lk+0][lr+64] = b1.x; Bs[lk+1][lr+64] = b1.y; Bs[lk+2][lr+64] = b1.z; Bs[lk+3][lr+64] = b1.w;
        __syncthreads();
        #pragma unroll
        for (int kk = 0; kk < 16; kk++) {
            float4 av0 = *(const float4*)&As[kk][ty*8];
            float4 av1 = *(const float4*)&As[kk][ty*8 + 4];
            float ar[8] = {av0.x, av0.y, av0.z, av0.w, av1.x, av1.y, av1.z, av1.w};
            float br[8];
            #pragma unroll
            for (int j = 0; j < 8; j++) br[j] = Bs[kk][tx + 16*j];
            #pragma unroll
            for (int i = 0; i < 8; i++)
                #pragma unroll
                for (int j = 0; j < 8; j++)
                    acc[i][j] = fmaf(ar[i], br[j], acc[i][j]);
        }
        Ap += 16; Bp += 16;
    }

    #pragma unroll
    for (int i = 0; i < 8; i++) {
        int row = row0 + ty*8 + i;
        #pragma unroll
        for (int j = 0; j < 8; j++) {
            int col = col0 + tx + 16*j;
            float v = acc[i][j] + bias[col];
            if (MODE == 0) {
                int b = row >> 11, t = row & (TT - 1);
                int h = col >> 7,  hd = col & 127;
                C[((size_t)(b*HH + h)*TT + t)*HDIM + hd] = v;
            } else {
                C[(size_t)row * DD + col] = v;
            }
        }
    }
}

// ---------------------------------------------------------------------------
// Causal flash attention, fp32. Block = one (b,h) x 64-query tile.
// 64q x 64k tiles, HD=128, online softmax, O accum in registers.
// ---------------------------------------------------------------------------
struct FlashSmem {
    float Qs[128][68];   // k-major (k, m), padded stride 68 (16B-aligned rows)
    float Ks[128][68];   // k-major (k, n)
    float Vs[64][132];   // (n, c)
    float Ss[64][65];    // scores / probs
    float row_m[64];
    float row_l[64];
    float row_fac[64];
};

__global__ void __launch_bounds__(256, 1) flash_attn_kernel() {
    extern __shared__ __align__(16) char raw[];
    FlashSmem& sm = *reinterpret_cast<FlashSmem*>(raw);

    int tid = threadIdx.x;
    int tx  = tid & 15;
    int ty  = tid >> 4;

    const int nqt = TT / 64;                  // 32
    int qtile = (nqt - 1) - blockIdx.x;       // big blocks first (load balance)
    int bh    = blockIdx.y;
    int q0    = qtile * 64;

    const float* Qg  = g_Q + ((size_t)bh * TT + q0) * HDIM;
    const float* Kg0 = g_K + (size_t)bh * TT * HDIM;
    const float* Vg0 = g_V + (size_t)bh * TT * HDIM;

    {   // load Q tile (transposed into smem)
        int row   = tid >> 2;
        int kbase = (tid & 3) * 4;
        #pragma unroll
        for (int it = 0; it < 8; it++) {
            int k = kbase + it * 16;
            float4 v = *(const float4*)(Qg + (size_t)row * HDIM + k);
            sm.Qs[k][row]   = v.x; sm.Qs[k+1][row] = v.y;
            sm.Qs[k+2][row] = v.z; sm.Qs[k+3][row] = v.w;
        }
    }
    if (tid < 64) { sm.row_m[tid] = -1e30f; sm.row_l[tid] = 0.0f; }

    float acc[4][8];
    #pragma unroll
    for (int i = 0; i < 4; i++)
        #pragma unroll
        for (int j = 0; j < 8; j++) acc[i][j] = 0.0f;

    const float scale = 0.08838834764831845f;   // 1/sqrt(128)

    for (int kt = 0; kt <= qtile; kt++) {
        int k0 = kt * 64;
        __syncthreads();
        {   // load K tile (transposed)
            int row   = tid >> 2;
            int kbase = (tid & 3) * 4;
            const float* Kg = Kg0 + (size_t)(k0 + row) * HDIM;
            #pragma unroll
            for (int it = 0; it < 8; it++) {
                int k = kbase + it * 16;
                float4 v = *(const float4*)(Kg + k);
                sm.Ks[k][row]   = v.x; sm.Ks[k+1][row] = v.y;
                sm.Ks[k+2][row] = v.z; sm.Ks[k+3][row] = v.w;
            }
        }
        {   // load V tile (row-major)
            #pragma unroll
            for (int it = 0; it < 8; it++) {
                int f   = it * 256 + tid;
                int row = f >> 5;
                int c   = (f & 31) * 4;
                float4 v = *(const float4*)(Vg0 + (size_t)(k0 + row) * HDIM + c);
                *(float4*)&sm.Vs[row][c] = v;
            }
        }
        __syncthreads();

        // ---- S = Q K^T (scaled, causal-masked on the diagonal tile) ----
        float sacc[4][4];
        #pragma unroll
        for (int i = 0; i < 4; i++)
            #pragma unroll
            for (int j = 0; j < 4; j++) sacc[i][j] = 0.0f;

        #pragma unroll 4
        for (int k = 0; k < 128; k++) {
            float4 a = *(const float4*)&sm.Qs[k][ty*4];
            float b0 = sm.Ks[k][tx];
            float b1 = sm.Ks[k][tx + 16];
            float b2 = sm.Ks[k][tx + 32];
            float b3 = sm.Ks[k][tx + 48];
            float ai[4] = {a.x, a.y, a.z, a.w};
            float bj[4] = {b0, b1, b2, b3};
            #pragma unroll
            for (int i = 0; i < 4; i++)
                #pragma unroll
                for (int j = 0; j < 4; j++)
                    sacc[i][j] = fmaf(ai[i], bj[j], sacc[i][j]);
        }
        bool diag = (kt == qtile);
        #pragma unroll
        for (int i = 0; i < 4; i++) {
            int r = ty*4 + i;
            #pragma unroll
            for (int j = 0; j < 4; j++) {
                int c = tx + 16*j;
                float sv = sacc[i][j] * scale;
                if (diag && (c > r)) sv = -1e30f;
                sm.Ss[r][c] = sv;
            }
        }
        __syncthreads();

        // ---- online softmax (4 threads per row) ----
        {
            int srow = tid >> 2;
            int sp   = (tid & 3) * 16;
            float mx = -1e30f;
            #pragma unroll
            for (int j = 0; j < 16; j++) mx = fmaxf(mx, sm.Ss[srow][sp + j]);
            mx = fmaxf(mx, __shfl_xor_sync(0xffffffffu, mx, 1));
            mx = fmaxf(mx, __shfl_xor_sync(0xffffffffu, mx, 2));
            float old_m = sm.row_m[srow];
            float new_m = fmaxf(old_m, mx);
            float s = 0.0f;
            #pragma unroll
            for (int j = 0; j < 16; j++) {
                float e = __expf(sm.Ss[srow][sp + j] - new_m);
                sm.Ss[srow][sp + j] = e;
                s += e;
            }
            s += __shfl_xor_sync(0xffffffffu, s, 1);
            s += __shfl_xor_sync(0xffffffffu, s, 2);
            if ((tid & 3) == 0) {
                float fac = __expf(old_m - new_m);
                sm.row_fac[srow] = fac;
                sm.row_l[srow]   = sm.row_l[srow] * fac + s;
                sm.row_m[srow]   = new_m;
            }
        }
        __syncthreads();

        // ---- rescale + O += P @ V ----
        float fr[4];
        #pragma unroll
        for (int i = 0; i < 4; i++) fr[i] = sm.row_fac[ty*4 + i];
        #pragma unroll
        for (int i = 0; i < 4; i++)
            #pragma unroll
            for (int j = 0; j < 8; j++) acc[i][j] *= fr[i];

        #pragma unroll 2
        for (int kc = 0; kc < 64; kc++) {
            float p[4];
            #pragma unroll
            for (int i = 0; i < 4; i++) p[i] = sm.Ss[ty*4 + i][kc];
            float v[8];
            #pragma unroll
            for (int j = 0; j < 8; j++) v[j] = sm.Vs[kc][tx + 16*j];
            #pragma unroll
            for (int i = 0; i < 4; i++)
                #pragma unroll
                for (int j = 0; j < 8; j++)
                    acc[i][j] = fmaf(p[i], v[j], acc[i][j]);
        }
    }

    // ---- epilogue: O / l -> g_O[b, t, h*128 + c] ----
    int b = bh >> 4;         // HH = 16
    int h = bh & 15;
    #pragma unroll
    for (int i = 0; i < 4; i++) {
        int q = q0 + ty*4 + i;
        float inv = 1.0f / sm.row_l[ty*4 + i];
        #pragma unroll
        for (int j = 0; j < 8; j++) {
            g_O[((size_t)(b*TT + q)) * DD + h*HDIM + tx + 16*j] = acc[i][j] * inv;
        }
    }
}

// ---------------------------------------------------------------------------
extern "C" void kernel_launch(void* const* d_in, const int* in_sizes, int n_in,
                              void* d_out, int out_size) {
    (void)in_sizes; (void)n_in; (void)out_size;
    const float* x       = (const float*)d_in[0];
    const float* Wq      = (const float*)d_in[1];
    const float* bq      = (const float*)d_in[2];
    const float* Wk      = (const float*)d_in[3];
    const float* bk      = (const float*)d_in[4];
    // d_in[5]=Wvq, d_in[6]=bvq, d_in[7]=v_keys: dead (top_k over full axis)
    const float* v_embed = (const float*)d_in[8];
    const float* Wo      = (const float*)d_in[9];
    const float* bo      = (const float*)d_in[10];
    float* out = (float*)d_out;

    float *qp = nullptr, *kp = nullptr, *op = nullptr;
    cudaGetSymbolAddress((void**)&qp, g_Q);
    cudaGetSymbolAddress((void**)&kp, g_K);
    cudaGetSymbolAddress((void**)&op, g_O);

    compute_c_kernel<<<DD/256, 256>>>(v_embed);
    compute_v_kernel<<<(BB*TT*DD)/256, 256>>>(x);

    dim3 gg(DD/128, MROWS/128);
    gemm_nt_kernel<0><<<gg, 256>>>(x, Wq, bq, qp);
    gemm_nt_kernel<0><<<gg, 256>>>(x, Wk, bk, kp);

    int smem = (int)sizeof(FlashSmem);
    cudaFuncSetAttribute(flash_attn_kernel,
                         cudaFuncAttributeMaxDynamicSharedMemorySize, smem);
    flash_attn_kernel<<<dim3(TT/64, BB*HH), 256, smem>>>();

    gemm_nt_kernel<1><<<gg, 256>>>(op, Wo, bo, out);
}

// round 2
// speedup vs baseline: 1.1129x; 1.1129x over previous
#include <cuda_runtime.h>
#include <math.h>

#define BB   2
#define TT   2048
#define DD   2048
#define HH   16
#define HDIM 128
#define MROWS (BB*TT)   // 4096

// Scratch (device globals: allocation-free per harness rules)
__device__ float g_Q[(size_t)BB*HH*TT*HDIM];
__device__ float g_K[(size_t)BB*HH*TT*HDIM];
__device__ float g_V[(size_t)BB*HH*TT*HDIM];
__device__ float g_O[(size_t)MROWS*DD];
__device__ float g_c[DD];

// ---------------------------------------------------------------------------
// tf32 helpers
// ---------------------------------------------------------------------------
__device__ __forceinline__ unsigned f2tf32(float f) {
    unsigned u;
    asm("cvt.rna.tf32.f32 %0, %1;" : "=r"(u) : "f"(f));
    return u;
}
__device__ __forceinline__ void split_tf32(float f, unsigned& hi, unsigned& lo) {
    hi = f2tf32(f);
    float r = f - __uint_as_float(hi);
    lo = f2tf32(r);
}
__device__ __forceinline__ void mma_tf32(float& d0, float& d1, float& d2, float& d3,
                                         unsigned a0, unsigned a1, unsigned a2, unsigned a3,
                                         unsigned b0, unsigned b1) {
    asm volatile(
        "mma.sync.aligned.m16n8k8.row.col.f32.tf32.tf32.f32 "
        "{%0,%1,%2,%3}, {%4,%5,%6,%7}, {%8,%9}, {%0,%1,%2,%3};\n"
        : "+f"(d0), "+f"(d1), "+f"(d2), "+f"(d3)
        : "r"(a0), "r"(a1), "r"(a2), "r"(a3), "r"(b0), "r"(b1));
}

// ---------------------------------------------------------------------------
// c[d] = 2 * sum_{j<4} v_embed[j][d]   (top_k with k == NVK selects everything)
// ---------------------------------------------------------------------------
__global__ void compute_c_kernel(const float* __restrict__ v_embed) {
    int d = blockIdx.x * 256 + threadIdx.x;
    if (d < DD)
        g_c[d] = 2.0f * (v_embed[d] + v_embed[DD + d] + v_embed[2*DD + d] + v_embed[3*DD + d]);
}

// ---------------------------------------------------------------------------
// V[b,h,t,hd] = x[b,t,h*128+hd] * c[h*128+hd]
// ---------------------------------------------------------------------------
__global__ void compute_v_kernel(const float* __restrict__ x) {
    int idx  = blockIdx.x * 256 + threadIdx.x;      // over B*T*D
    int dcol = idx & (DD - 1);
    int bt   = idx >> 11;                           // DD = 2048
    int b    = bt >> 11;                            // TT = 2048
    int t    = bt & (TT - 1);
    int h    = dcol >> 7;
    int hd   = dcol & 127;
    g_V[((size_t)(b*HH + h)*TT + t)*HDIM + hd] = x[idx] * g_c[dcol];
}

// ---------------------------------------------------------------------------
// NT GEMM on tensor cores (tf32 3-term split for ~fp32 accuracy):
// C[M=4096,N=2048] = A[M,K=2048] * B[N,K]^T + bias[N]
// CTA tile 128x128x16, 256 threads = 8 warps (4x2), warp tile 32x64.
// SMEM [m][k]/[n][k] with stride 20 -> conflict-free frag loads, STS.128 stage.
// MODE 0: scatter to per-head layout [b,h,t,hd]; MODE 1: row-major [M][N]
// ---------------------------------------------------------------------------
template<int MODE>
__global__ void __launch_bounds__(256, 2) gemm_tc_kernel(
    const float* __restrict__ A, const float* __restrict__ Bm,
    const float* __restrict__ bias, float* __restrict__ C)
{
    __shared__ __align__(16) float As[128][20];
    __shared__ __align__(16) float Bs[128][20];
    const int K = DD;

    int tid  = threadIdx.x;
    int lane = tid & 31;
    int warp = tid >> 5;
    int wm   = warp >> 1;         // 0..3
    int wn   = warp & 1;          // 0..1
    int gid  = lane >> 2;         // 0..7
    int tig  = lane & 3;          // 0..3

    int row0 = blockIdx.y * 128;
    int col0 = blockIdx.x * 128;

    int lr = tid >> 2;            // 0..63
    int lk = (tid & 3) * 4;       // 0,4,8,12

    const float* Ap = A  + (size_t)(row0 + lr) * K + lk;
    const float* Bp = Bm + (size_t)(col0 + lr) * K + lk;

    float acc[2][8][4];
    #pragma unroll
    for (int mi = 0; mi < 2; mi++)
        #pragma unroll
        for (int ni = 0; ni < 8; ni++)
            #pragma unroll
            for (int r = 0; r < 4; r++) acc[mi][ni][r] = 0.0f;

    for (int kb = 0; kb < K; kb += 16) {
        float4 a0 = *(const float4*)Ap;
        float4 a1 = *(const float4*)(Ap + (size_t)64 * K);
        float4 b0 = *(const float4*)Bp;
        float4 b1 = *(const float4*)(Bp + (size_t)64 * K);
        __syncthreads();
        *(float4*)&As[lr][lk]      = a0;
        *(float4*)&As[lr + 64][lk] = a1;
        *(float4*)&Bs[lr][lk]      = b0;
        *(float4*)&Bs[lr + 64][lk] = b1;
        __syncthreads();

        #pragma unroll
        for (int ks = 0; ks < 2; ks++) {
            int k0 = ks * 8;
            // A fragments (hi/lo) for both m16 tiles
            unsigned ahi[2][4], alo[2][4];
            #pragma unroll
            for (int mi = 0; mi < 2; mi++) {
                int m0 = wm * 32 + mi * 16;
                float f0 = As[m0 + gid    ][k0 + tig];
                float f1 = As[m0 + gid + 8][k0 + tig];
                float f2 = As[m0 + gid    ][k0 + tig + 4];
                float f3 = As[m0 + gid + 8][k0 + tig + 4];
                split_tf32(f0, ahi[mi][0], alo[mi][0]);
                split_tf32(f1, ahi[mi][1], alo[mi][1]);
                split_tf32(f2, ahi[mi][2], alo[mi][2]);
                split_tf32(f3, ahi[mi][3], alo[mi][3]);
            }
            #pragma unroll
            for (int ni = 0; ni < 8; ni++) {
                int n0 = wn * 64 + ni * 8;
                float g0 = Bs[n0 + gid][k0 + tig];
                float g1 = Bs[n0 + gid][k0 + tig + 4];
                unsigned bhi0, blo0, bhi1, blo1;
                split_tf32(g0, bhi0, blo0);
                split_tf32(g1, bhi1, blo1);
                #pragma unroll
                for (int mi = 0; mi < 2; mi++) {
                    float* d = acc[mi][ni];
                    mma_tf32(d[0], d[1], d[2], d[3],
                             ahi[mi][0], ahi[mi][1], ahi[mi][2], ahi[mi][3], bhi0, bhi1);
                    mma_tf32(d[0], d[1], d[2], d[3],
                             alo[mi][0], alo[mi][1], alo[mi][2], alo[mi][3], bhi0, bhi1);
                    mma_tf32(d[0], d[1], d[2], d[3],
                             ahi[mi][0], ahi[mi][1], ahi[mi][2], ahi[mi][3], blo0, blo1);
                }
            }
        }
        Ap += 16; Bp += 16;
    }

    // epilogue
    #pragma unroll
    for (int mi = 0; mi < 2; mi++) {
        #pragma unroll
        for (int ni = 0; ni < 8; ni++) {
            int colA = col0 + wn * 64 + ni * 8 + tig * 2;
            #pragma unroll
            for (int r = 0; r < 4; r++) {
                int row = row0 + wm * 32 + mi * 16 + gid + ((r >> 1) ? 8 : 0);
                int col = colA + (r & 1);
                float v = acc[mi][ni][r] + bias[col];
                if (MODE == 0) {
                    int b = row >> 11, t = row & (TT - 1);
                    int h = col >> 7,  hd = col & 127;
                    C[((size_t)(b*HH + h)*TT + t)*HDIM + hd] = v;
                } else {
                    C[(size_t)row * DD + col] = v;
                }
            }
        }
    }
}

// ---------------------------------------------------------------------------
// Causal flash attention, fp32. Block = one (b,h) x 64-query tile.
// 64q x 64k tiles, HD=128, online softmax, O accum in registers.
// ---------------------------------------------------------------------------
struct FlashSmem {
    float Qs[128][68];   // k-major (k, m)
    float Ks[128][68];   // k-major (k, n)
    float Vs[64][132];   // (n, c)
    float Ss[64][65];    // scores / probs
    float row_m[64];
    float row_l[64];
    float row_fac[64];
};

__global__ void __launch_bounds__(256, 1) flash_attn_kernel() {
    extern __shared__ __align__(16) char raw[];
    FlashSmem& sm = *reinterpret_cast<FlashSmem*>(raw);

    int tid = threadIdx.x;
    int tx  = tid & 15;
    int ty  = tid >> 4;

    const int nqt = TT / 64;                  // 32
    int qtile = (nqt - 1) - blockIdx.x;       // big blocks first (load balance)
    int bh    = blockIdx.y;
    int q0    = qtile * 64;

    const float* Qg  = g_Q + ((size_t)bh * TT + q0) * HDIM;
    const float* Kg0 = g_K + (size_t)bh * TT * HDIM;
    const float* Vg0 = g_V + (size_t)bh * TT * HDIM;

    {   // load Q tile (transposed into smem)
        int row   = tid >> 2;
        int kbase = (tid & 3) * 4;
        #pragma unroll
        for (int it = 0; it < 8; it++) {
            int k = kbase + it * 16;
            float4 v = *(const float4*)(Qg + (size_t)row * HDIM + k);
            sm.Qs[k][row]   = v.x; sm.Qs[k+1][row] = v.y;
            sm.Qs[k+2][row] = v.z; sm.Qs[k+3][row] = v.w;
        }
    }
    if (tid < 64) { sm.row_m[tid] = -1e30f; sm.row_l[tid] = 0.0f; }

    float acc[4][8];
    #pragma unroll
    for (int i = 0; i < 4; i++)
        #pragma unroll
        for (int j = 0; j < 8; j++) acc[i][j] = 0.0f;

    const float scale = 0.08838834764831845f;   // 1/sqrt(128)

    for (int kt = 0; kt <= qtile; kt++) {
        int k0 = kt * 64;
        __syncthreads();
        {   // load K tile (transposed)
            int row   = tid >> 2;
            int kbase = (tid & 3) * 4;
            const float* Kg = Kg0 + (size_t)(k0 + row) * HDIM;
            #pragma unroll
            for (int it = 0; it < 8; it++) {
                int k = kbase + it * 16;
                float4 v = *(const float4*)(Kg + k);
                sm.Ks[k][row]   = v.x; sm.Ks[k+1][row] = v.y;
                sm.Ks[k+2][row] = v.z; sm.Ks[k+3][row] = v.w;
            }
        }
        {   // load V tile (row-major)
            #pragma unroll
            for (int it = 0; it < 8; it++) {
                int f   = it * 256 + tid;
                int row = f >> 5;
                int c   = (f & 31) * 4;
                float4 v = *(const float4*)(Vg0 + (size_t)(k0 + row) * HDIM + c);
                *(float4*)&sm.Vs[row][c] = v;
            }
        }
        __syncthreads();

        // ---- S = Q K^T (scaled, causal-masked on the diagonal tile) ----
        float sacc[4][4];
        #pragma unroll
        for (int i = 0; i < 4; i++)
            #pragma unroll
            for (int j = 0; j < 4; j++) sacc[i][j] = 0.0f;

        #pragma unroll 4
        for (int k = 0; k < 128; k++) {
            float4 a = *(const float4*)&sm.Qs[k][ty*4];
            float b0 = sm.Ks[k][tx];
            float b1 = sm.Ks[k][tx + 16];
            float b2 = sm.Ks[k][tx + 32];
            float b3 = sm.Ks[k][tx + 48];
            float ai[4] = {a.x, a.y, a.z, a.w};
            float bj[4] = {b0, b1, b2, b3};
            #pragma unroll
            for (int i = 0; i < 4; i++)
                #pragma unroll
                for (int j = 0; j < 4; j++)
                    sacc[i][j] = fmaf(ai[i], bj[j], sacc[i][j]);
        }
        bool diag = (kt == qtile);
        #pragma unroll
        for (int i = 0; i < 4; i++) {
            int r = ty*4 + i;
            #pragma unroll
            for (int j = 0; j < 4; j++) {
                int c = tx + 16*j;
                float sv = sacc[i][j] * scale;
                if (diag && (c > r)) sv = -1e30f;
                sm.Ss[r][c] = sv;
            }
        }
        __syncthreads();

        // ---- online softmax (4 threads per row) ----
        {
            int srow = tid >> 2;
            int sp   = (tid & 3) * 16;
            float mx = -1e30f;
            #pragma unroll
            for (int j = 0; j < 16; j++) mx = fmaxf(mx, sm.Ss[srow][sp + j]);
            mx = fmaxf(mx, __shfl_xor_sync(0xffffffffu, mx, 1));
            mx = fmaxf(mx, __shfl_xor_sync(0xffffffffu, mx, 2));
            float old_m = sm.row_m[srow];
            float new_m = fmaxf(old_m, mx);
            float s = 0.0f;
            #pragma unroll
            for (int j = 0; j < 16; j++) {
                float e = __expf(sm.Ss[srow][sp + j] - new_m);
                sm.Ss[srow][sp + j] = e;
                s += e;
            }
            s += __shfl_xor_sync(0xffffffffu, s, 1);
            s += __shfl_xor_sync(0xffffffffu, s, 2);
            if ((tid & 3) == 0) {
                float fac = __expf(old_m - new_m);
                sm.row_fac[srow] = fac;
                sm.row_l[srow]   = sm.row_l[srow] * fac + s;
                sm.row_m[srow]   = new_m;
            }
        }
        __syncthreads();

        // ---- rescale + O += P @ V ----
        float fr[4];
        #pragma unroll
        for (int i = 0; i < 4; i++) fr[i] = sm.row_fac[ty*4 + i];
        #pragma unroll
        for (int i = 0; i < 4; i++)
            #pragma unroll
            for (int j = 0; j < 8; j++) acc[i][j] *= fr[i];

        #pragma unroll 2
        for (int kc = 0; kc < 64; kc++) {
            float p[4];
            #pragma unroll
            for (int i = 0; i < 4; i++) p[i] = sm.Ss[ty*4 + i][kc];
            float v[8];
            #pragma unroll
            for (int j = 0; j < 8; j++) v[j] = sm.Vs[kc][tx + 16*j];
            #pragma unroll
            for (int i = 0; i < 4; i++)
                #pragma unroll
                for (int j = 0; j < 8; j++)
                    acc[i][j] = fmaf(p[i], v[j], acc[i][j]);
        }
    }

    // ---- epilogue: O / l -> g_O[b, t, h*128 + c] ----
    int b = bh >> 4;         // HH = 16
    int h = bh & 15;
    #pragma unroll
    for (int i = 0; i < 4; i++) {
        int q = q0 + ty*4 + i;
        float inv = 1.0f / sm.row_l[ty*4 + i];
        #pragma unroll
        for (int j = 0; j < 8; j++) {
            g_O[((size_t)(b*TT + q)) * DD + h*HDIM + tx + 16*j] = acc[i][j] * inv;
        }
    }
}

// ---------------------------------------------------------------------------
extern "C" void kernel_launch(void* const* d_in, const int* in_sizes, int n_in,
                              void* d_out, int out_size) {
    (void)in_sizes; (void)n_in; (void)out_size;
    const float* x       = (const float*)d_in[0];
    const float* Wq      = (const float*)d_in[1];
    const float* bq      = (const float*)d_in[2];
    const float* Wk      = (const float*)d_in[3];
    const float* bk      = (const float*)d_in[4];
    // d_in[5]=Wvq, d_in[6]=bvq, d_in[7]=v_keys: dead (top_k over full axis)
    const float* v_embed = (const float*)d_in[8];
    const float* Wo      = (const float*)d_in[9];
    const float* bo      = (const float*)d_in[10];
    float* out = (float*)d_out;

    float *qp = nullptr, *kp = nullptr, *op = nullptr;
    cudaGetSymbolAddress((void**)&qp, g_Q);
    cudaGetSymbolAddress((void**)&kp, g_K);
    cudaGetSymbolAddress((void**)&op, g_O);

    compute_c_kernel<<<DD/256, 256>>>(v_embed);
    compute_v_kernel<<<(BB*TT*DD)/256, 256>>>(x);

    dim3 gg(DD/128, MROWS/128);
    gemm_tc_kernel<0><<<gg, 256>>>(x, Wq, bq, qp);
    gemm_tc_kernel<0><<<gg, 256>>>(x, Wk, bk, kp);

    int smem = (int)sizeof(FlashSmem);
    cudaFuncSetAttribute(flash_attn_kernel,
                         cudaFuncAttributeMaxDynamicSharedMemorySize, smem);
    flash_attn_kernel<<<dim3(TT/64, BB*HH), 256, smem>>>();

    gemm_tc_kernel<1><<<gg, 256>>>(op, Wo, bo, out);
}

// round 3
// speedup vs baseline: 1.8707x; 1.6809x over previous
#include <cuda_runtime.h>
#include <math.h>

#define BB   2
#define TT   2048
#define DD   2048
#define HH   16
#define HDIM 128
#define MROWS (BB*TT)   // 4096

// Scratch (device globals: allocation-free per harness rules)
__device__ float g_Q[(size_t)BB*HH*TT*HDIM];
__device__ float g_K[(size_t)BB*HH*TT*HDIM];
__device__ float g_V[(size_t)BB*HH*TT*HDIM];
__device__ float g_O[(size_t)MROWS*DD];
__device__ float g_c[DD];

// ---------------------------------------------------------------------------
// bf16 split helpers: a = hi + lo, hi = truncate-to-bf16(a) (exact mask),
// lo = rn-bf16(a - hi).  Pair-packed: word = {hi16(a1), hi16(a0)} etc.
// ---------------------------------------------------------------------------
__device__ __forceinline__ void bsplit2(float a0, float a1, unsigned& h, unsigned& l) {
    unsigned u0 = __float_as_uint(a0), u1 = __float_as_uint(a1);
    asm("prmt.b32 %0, %1, %2, 0x7632;" : "=r"(h) : "r"(u0), "r"(u1));
    float l0 = a0 - __uint_as_float(u0 & 0xffff0000u);
    float l1 = a1 - __uint_as_float(u1 & 0xffff0000u);
    asm("cvt.rn.bf16x2.f32 %0, %1, %2;" : "=r"(l) : "f"(l1), "f"(l0));
}

__device__ __forceinline__ void mma_bf16(float& d0, float& d1, float& d2, float& d3,
                                         unsigned a0, unsigned a1, unsigned a2, unsigned a3,
                                         unsigned b0, unsigned b1) {
    asm volatile(
        "mma.sync.aligned.m16n8k16.row.col.f32.bf16.bf16.f32 "
        "{%0,%1,%2,%3}, {%4,%5,%6,%7}, {%8,%9}, {%0,%1,%2,%3};\n"
        : "+f"(d0), "+f"(d1), "+f"(d2), "+f"(d3)
        : "r"(a0), "r"(a1), "r"(a2), "r"(a3), "r"(b0), "r"(b1));
}

// ---------------------------------------------------------------------------
// c[d] = 2 * sum_{j<4} v_embed[j][d]   (top_k with k == NVK selects everything)
// ---------------------------------------------------------------------------
__global__ void compute_c_kernel(const float* __restrict__ v_embed) {
    int d = blockIdx.x * 256 + threadIdx.x;
    if (d < DD)
        g_c[d] = 2.0f * (v_embed[d] + v_embed[DD + d] + v_embed[2*DD + d] + v_embed[3*DD + d]);
}

// V[b,h,t,hd] = x[b,t,h*128+hd] * c[h*128+hd]
__global__ void compute_v_kernel(const float* __restrict__ x) {
    int idx  = blockIdx.x * 256 + threadIdx.x;
    int dcol = idx & (DD - 1);
    int bt   = idx >> 11;
    int b    = bt >> 11;
    int t    = bt & (TT - 1);
    int h    = dcol >> 7;
    int hd   = dcol & 127;
    g_V[((size_t)(b*HH + h)*TT + t)*HDIM + hd] = x[idx] * g_c[dcol];
}

// ---------------------------------------------------------------------------
// NT GEMM, bf16 3-term (fp32-accurate): C[4096,2048] = A*B^T + bias
// CTA 128x128x32, 256 thr, 8 warps (4x2), warp tile 32x64, double-buffered.
// smem: per stage Ah/Al/Bh/Bl as bf16 [128][40] (kpad 40 -> conflict-free).
// ---------------------------------------------------------------------------
#define GS_STAGE  40960            // 4 * 128*40*2 bytes
#define GS_AH 0
#define GS_AL 10240
#define GS_BH 20480
#define GS_BL 30720

template<int MODE>
__global__ void __launch_bounds__(256, 2) gemm_bf16_kernel(
    const float* __restrict__ A, const float* __restrict__ Bm,
    const float* __restrict__ bias, float* __restrict__ C)
{
    extern __shared__ __align__(16) char gsm[];
    const int K = DD;

    int tid  = threadIdx.x;
    int lane = tid & 31;
    int warp = tid >> 5;
    int wm   = warp >> 1;
    int wn   = warp & 1;
    int gid  = lane >> 2;
    int tig  = lane & 3;

    int row0 = blockIdx.y * 128;
    int col0 = blockIdx.x * 128;

    int lr = tid >> 1;                 // 0..127
    int kq = (tid & 1) * 16;           // 0 / 16

    const float* Aq = A  + (size_t)(row0 + lr) * K + kq;
    const float* Bq = Bm + (size_t)(col0 + lr) * K + kq;

    float acc[2][8][4];
    #pragma unroll
    for (int mi = 0; mi < 2; mi++)
        #pragma unroll
        for (int ni = 0; ni < 8; ni++)
            #pragma unroll
            for (int r = 0; r < 4; r++) acc[mi][ni][r] = 0.0f;

    // staging helper lambdas (manual)
    unsigned* sm_u = (unsigned*)gsm;

    // prolog: stage 0
    {
        float4 va[4], vb[4];
        #pragma unroll
        for (int j = 0; j < 4; j++) {
            va[j] = *(const float4*)(Aq + 4*j);
            vb[j] = *(const float4*)(Bq + 4*j);
        }
        unsigned ah[8], al[8], bh[8], bl[8];
        #pragma unroll
        for (int j = 0; j < 4; j++) {
            bsplit2(va[j].x, va[j].y, ah[2*j],   al[2*j]);
            bsplit2(va[j].z, va[j].w, ah[2*j+1], al[2*j+1]);
            bsplit2(vb[j].x, vb[j].y, bh[2*j],   bl[2*j]);
            bsplit2(vb[j].z, vb[j].w, bh[2*j+1], bl[2*j+1]);
        }
        int wo = lr*20 + kq/2;   // word offset in [128][20] word array
        #pragma unroll
        for (int j = 0; j < 2; j++) {
            *(uint4*)&sm_u[(GS_AH>>2) + wo + 4*j] = make_uint4(ah[4*j],ah[4*j+1],ah[4*j+2],ah[4*j+3]);
            *(uint4*)&sm_u[(GS_AL>>2) + wo + 4*j] = make_uint4(al[4*j],al[4*j+1],al[4*j+2],al[4*j+3]);
            *(uint4*)&sm_u[(GS_BH>>2) + wo + 4*j] = make_uint4(bh[4*j],bh[4*j+1],bh[4*j+2],bh[4*j+3]);
            *(uint4*)&sm_u[(GS_BL>>2) + wo + 4*j] = make_uint4(bl[4*j],bl[4*j+1],bl[4*j+2],bl[4*j+3]);
        }
    }

    const int NKB = K / 32;   // 64
    for (int kb = 0; kb < NKB; kb++) {
        __syncthreads();

        float4 va[4], vb[4];
        if (kb + 1 < NKB) {
            int ko = (kb + 1) * 32;
            #pragma unroll
            for (int j = 0; j < 4; j++) {
                va[j] = *(const float4*)(Aq + ko + 4*j);
                vb[j] = *(const float4*)(Bq + ko + 4*j);
            }
        }

        // compute on stage kb&1
        unsigned* AHW = sm_u + (((kb & 1) * GS_STAGE + GS_AH) >> 2);
        unsigned* ALW = sm_u + (((kb & 1) * GS_STAGE + GS_AL) >> 2);
        unsigned* BHW = sm_u + (((kb & 1) * GS_STAGE + GS_BH) >> 2);
        unsigned* BLW = sm_u + (((kb & 1) * GS_STAGE + GS_BL) >> 2);

        #pragma unroll
        for (int ks = 0; ks < 2; ks++) {
            int kw = ks * 8;
            unsigned ah[2][4], al[2][4];
            #pragma unroll
            for (int mi = 0; mi < 2; mi++) {
                int m = wm*32 + mi*16;
                int o0 = (m + gid)     * 20 + kw + tig;
                int o1 = (m + gid + 8) * 20 + kw + tig;
                ah[mi][0] = AHW[o0];     ah[mi][1] = AHW[o1];
                ah[mi][2] = AHW[o0 + 4]; ah[mi][3] = AHW[o1 + 4];
                al[mi][0] = ALW[o0];     al[mi][1] = ALW[o1];
                al[mi][2] = ALW[o0 + 4]; al[mi][3] = ALW[o1 + 4];
            }
            #pragma unroll
            for (int ni = 0; ni < 8; ni++) {
                int n = wn*64 + ni*8;
                int ob = (n + gid) * 20 + kw + tig;
                unsigned bh0 = BHW[ob], bh1 = BHW[ob + 4];
                unsigned bl0 = BLW[ob], bl1 = BLW[ob + 4];
                #pragma unroll
                for (int mi = 0; mi < 2; mi++) {
                    float* d = acc[mi][ni];
                    mma_bf16(d[0],d[1],d[2],d[3], ah[mi][0],ah[mi][1],ah[mi][2],ah[mi][3], bh0,bh1);
                    mma_bf16(d[0],d[1],d[2],d[3], al[mi][0],al[mi][1],al[mi][2],al[mi][3], bh0,bh1);
                    mma_bf16(d[0],d[1],d[2],d[3], ah[mi][0],ah[mi][1],ah[mi][2],ah[mi][3], bl0,bl1);
                }
            }
        }

        if (kb + 1 < NKB) {
            unsigned ah[8], al[8], bh[8], bl[8];
            #pragma unroll
            for (int j = 0; j < 4; j++) {
                bsplit2(va[j].x, va[j].y, ah[2*j],   al[2*j]);
                bsplit2(va[j].z, va[j].w, ah[2*j+1], al[2*j+1]);
                bsplit2(vb[j].x, vb[j].y, bh[2*j],   bl[2*j]);
                bsplit2(vb[j].z, vb[j].w, bh[2*j+1], bl[2*j+1]);
            }
            unsigned* DST = sm_u + ((((kb + 1) & 1) * GS_STAGE) >> 2);
            int wo = lr*20 + kq/2;
            #pragma unroll
            for (int j = 0; j < 2; j++) {
                *(uint4*)&DST[(GS_AH>>2) + wo + 4*j] = make_uint4(ah[4*j],ah[4*j+1],ah[4*j+2],ah[4*j+3]);
                *(uint4*)&DST[(GS_AL>>2) + wo + 4*j] = make_uint4(al[4*j],al[4*j+1],al[4*j+2],al[4*j+3]);
                *(uint4*)&DST[(GS_BH>>2) + wo + 4*j] = make_uint4(bh[4*j],bh[4*j+1],bh[4*j+2],bh[4*j+3]);
                *(uint4*)&DST[(GS_BL>>2) + wo + 4*j] = make_uint4(bl[4*j],bl[4*j+1],bl[4*j+2],bl[4*j+3]);
            }
        }
    }

    // epilogue
    #pragma unroll
    for (int mi = 0; mi < 2; mi++) {
        #pragma unroll
        for (int ni = 0; ni < 8; ni++) {
            int colA = col0 + wn*64 + ni*8 + tig*2;
            #pragma unroll
            for (int r = 0; r < 4; r++) {
                int row = row0 + wm*32 + mi*16 + gid + ((r >> 1) ? 8 : 0);
                int col = colA + (r & 1);
                float v = acc[mi][ni][r] + bias[col];
                if (MODE == 0) {
                    int b = row >> 11, t = row & (TT - 1);
                    int h = col >> 7,  hd = col & 127;
                    C[((size_t)(b*HH + h)*TT + t)*HDIM + hd] = v;
                } else {
                    C[(size_t)row * DD + col] = v;
                }
            }
        }
    }
}

// ---------------------------------------------------------------------------
// Flash attention on tensor cores (bf16 3-term), causal.
// CTA: 256 thr = 8 warps. qtile = 128, ktile = 64, HD = 128.
// QK warp tile 32x32 (4x2); PV warp tile 32x64 (4x2).
// smem word layouts (bf16 pairs packed in 32-bit words along k):
//   Q hi/lo [128][68w]  K hi/lo [64][68w]  V hi/lo [128 hd][36w] (transposed)
//   S f32 [128][68]     P hi/lo [128][36w]  row_m/l/fac [128]
// ---------------------------------------------------------------------------
#define FO_QH 0
#define FO_QL (FO_QH + 128*68*4)
#define FO_KH (FO_QL + 128*68*4)
#define FO_KL (FO_KH + 64*68*4)
#define FO_VH (FO_KL + 64*68*4)
#define FO_VL (FO_VH + 128*36*4)
#define FO_SS (FO_VL + 128*36*4)
#define FO_PH (FO_SS + 128*68*4)
#define FO_PL (FO_PH + 128*36*4)
#define FO_RM (FO_PL + 128*36*4)
#define FO_RL (FO_RM + 128*4)
#define FO_RF (FO_RL + 128*4)
#define FO_END (FO_RF + 128*4)

__global__ void __launch_bounds__(256, 1) flash_tc_kernel() {
    extern __shared__ __align__(16) char fsm[];
    unsigned* QHW = (unsigned*)(fsm + FO_QH);
    unsigned* QLW = (unsigned*)(fsm + FO_QL);
    unsigned* KHW = (unsigned*)(fsm + FO_KH);
    unsigned* KLW = (unsigned*)(fsm + FO_KL);
    unsigned* VHW = (unsigned*)(fsm + FO_VH);
    unsigned* VLW = (unsigned*)(fsm + FO_VL);
    float*    SS  = (float*)   (fsm + FO_SS);
    unsigned* PHW = (unsigned*)(fsm + FO_PH);
    unsigned* PLW = (unsigned*)(fsm + FO_PL);
    float*    RM  = (float*)   (fsm + FO_RM);
    float*    RL  = (float*)   (fsm + FO_RL);
    float*    RF  = (float*)   (fsm + FO_RF);

    int tid  = threadIdx.x;
    int lane = tid & 31;
    int warp = tid >> 5;
    int wm   = warp >> 1;          // 0..3
    int wn   = warp & 1;           // 0..1
    int gid  = lane >> 2;
    int tig  = lane & 3;

    int qtile = 15 - blockIdx.x;   // reverse: heavy tiles first
    int bh    = blockIdx.y;
    int q0    = qtile * 128;

    const float* Qg = g_Q + ((size_t)bh * TT + q0) * HDIM;
    const float* Kg = g_K + (size_t)bh * TT * HDIM;
    const float* Vg = g_V + (size_t)bh * TT * HDIM;

    // ---- stage Q (128 x 128) -> bf16 hi/lo, once ----
    {
        int r  = tid >> 1;
        int kq = (tid & 1) * 64;
        const float* src = Qg + (size_t)r * HDIM + kq;
        int wo = r*68 + kq/2;
        #pragma unroll
        for (int j = 0; j < 8; j++) {   // 8 x (8 floats -> 4 words)
            float4 v0 = *(const float4*)(src + 8*j);
            float4 v1 = *(const float4*)(src + 8*j + 4);
            unsigned h0,l0,h1,l1,h2,l2,h3,l3;
            bsplit2(v0.x, v0.y, h0, l0);
            bsplit2(v0.z, v0.w, h1, l1);
            bsplit2(v1.x, v1.y, h2, l2);
            bsplit2(v1.z, v1.w, h3, l3);
            *(uint4*)&QHW[wo + 4*j] = make_uint4(h0,h1,h2,h3);
            *(uint4*)&QLW[wo + 4*j] = make_uint4(l0,l1,l2,l3);
        }
    }
    if (tid < 128) { RM[tid] = -1e30f; RL[tid] = 0.0f; }

    float oacc[2][8][4];
    #pragma unroll
    for (int mi = 0; mi < 2; mi++)
        #pragma unroll
        for (int ni = 0; ni < 8; ni++)
            #pragma unroll
            for (int r = 0; r < 4; r++) oacc[mi][ni][r] = 0.0f;

    const float scale = 0.08838834764831845f;   // 1/sqrt(128)
    int nkt = 2*qtile + 2;

    for (int kt = 0; kt < nkt; kt++) {
        int k0 = kt * 64;
        __syncthreads();   // prev PV done; staging buffers free

        // ---- stage K (64 x 128) ----
        {
            int r  = tid >> 2;
            int kq = (tid & 3) * 32;
            const float* src = Kg + (size_t)(k0 + r) * HDIM + kq;
            int wo = r*68 + kq/2;
            #pragma unroll
            for (int j = 0; j < 4; j++) {
                float4 v0 = *(const float4*)(src + 8*j);
                float4 v1 = *(const float4*)(src + 8*j + 4);
                unsigned h0,l0,h1,l1,h2,l2,h3,l3;
                bsplit2(v0.x, v0.y, h0, l0);
                bsplit2(v0.z, v0.w, h1, l1);
                bsplit2(v1.x, v1.y, h2, l2);
                bsplit2(v1.z, v1.w, h3, l3);
                *(uint4*)&KHW[wo + 4*j] = make_uint4(h0,h1,h2,h3);
                *(uint4*)&KLW[wo + 4*j] = make_uint4(l0,l1,l2,l3);
            }
        }
        // ---- stage V transposed: VW[hd][t-pair] ----
        {
            int n = tid & 127;
            int tb = (tid >> 7) * 2;   // 0 or 2
            #pragma unroll
            for (int p = 0; p < 16; p++) {
                int t = p*4 + tb;
                float v0 = Vg[(size_t)(k0 + t)     * HDIM + n];
                float v1 = Vg[(size_t)(k0 + t + 1) * HDIM + n];
                unsigned h, l;
                bsplit2(v0, v1, h, l);
                VHW[n*36 + (t >> 1)] = h;
                VLW[n*36 + (t >> 1)] = l;
            }
        }
        __syncthreads();

        // ---- S = Q K^T : warp tile 32(m) x 32(n) ----
        float sacc[2][4][4];
        #pragma unroll
        for (int mi = 0; mi < 2; mi++)
            #pragma unroll
            for (int ni = 0; ni < 4; ni++)
                #pragma unroll
                for (int r = 0; r < 4; r++) sacc[mi][ni][r] = 0.0f;

        #pragma unroll
        for (int ks = 0; ks < 8; ks++) {
            int kw = ks * 8;
            unsigned ah[2][4], al[2][4];
            #pragma unroll
            for (int mi = 0; mi < 2; mi++) {
                int m = wm*32 + mi*16;
                int o0 = (m + gid)     * 68 + kw + tig;
                int o1 = (m + gid + 8) * 68 + kw + tig;
                ah[mi][0] = QHW[o0];     ah[mi][1] = QHW[o1];
                ah[mi][2] = QHW[o0 + 4]; ah[mi][3] = QHW[o1 + 4];
                al[mi][0] = QLW[o0];     al[mi][1] = QLW[o1];
                al[mi][2] = QLW[o0 + 4]; al[mi][3] = QLW[o1 + 4];
            }
            #pragma unroll
            for (int ni = 0; ni < 4; ni++) {
                int n = wn*32 + ni*8;
                int ob = (n + gid) * 68 + kw + tig;
                unsigned bh0 = KHW[ob], bh1 = KHW[ob + 4];
                unsigned bl0 = KLW[ob], bl1 = KLW[ob + 4];
                #pragma unroll
                for (int mi = 0; mi < 2; mi++) {
                    float* d = sacc[mi][ni];
                    mma_bf16(d[0],d[1],d[2],d[3], ah[mi][0],ah[mi][1],ah[mi][2],ah[mi][3], bh0,bh1);
                    mma_bf16(d[0],d[1],d[2],d[3], al[mi][0],al[mi][1],al[mi][2],al[mi][3], bh0,bh1);
                    mma_bf16(d[0],d[1],d[2],d[3], ah[mi][0],ah[mi][1],ah[mi][2],ah[mi][3], bl0,bl1);
                }
            }
        }
        // store S (scaled, masked)
        bool diag = (k0 + 63 > q0);
        #pragma unroll
        for (int mi = 0; mi < 2; mi++) {
            #pragma unroll
            for (int ni = 0; ni < 4; ni++) {
                #pragma unroll
                for (int r = 0; r < 4; r++) {
                    int row = wm*32 + mi*16 + gid + ((r >> 1) ? 8 : 0);
                    int col = wn*32 + ni*8 + tig*2 + (r & 1);
                    float sv = sacc[mi][ni][r] * scale;
                    if (diag && (k0 + col > q0 + row)) sv = -1e30f;
                    SS[row*68 + col] = sv;
                }
            }
        }
        __syncthreads();

        // ---- online softmax: 2 threads per row ----
        {
            int row = tid >> 1;
            int kq  = (tid & 1) * 32;
            float e[32];
            #pragma unroll
            for (int j = 0; j < 8; j++)
                *(float4*)&e[4*j] = *(const float4*)&SS[row*68 + kq + 4*j];
            float mx = -1e30f;
            #pragma unroll
            for (int j = 0; j < 32; j++) mx = fmaxf(mx, e[j]);
            mx = fmaxf(mx, __shfl_xor_sync(0xffffffffu, mx, 1));
            float old_m = RM[row];
            float new_m = fmaxf(old_m, mx);
            float s = 0.0f;
            #pragma unroll
            for (int j = 0; j < 32; j++) {
                e[j] = __expf(e[j] - new_m);
                s += e[j];
            }
            s += __shfl_xor_sync(0xffffffffu, s, 1);
            if ((tid & 1) == 0) {
                float fac = __expf(old_m - new_m);
                RF[row] = fac;
                RL[row] = RL[row] * fac + s;
                RM[row] = new_m;
            }
            // P = exp values -> bf16 hi/lo pairs
            int wo = row*36 + kq/2;
            #pragma unroll
            for (int j = 0; j < 16; j++) {
                unsigned h, l;
                bsplit2(e[2*j], e[2*j+1], h, l);
                PHW[wo + j] = h;
                PLW[wo + j] = l;
            }
        }
        __syncthreads();

        // ---- O rescale + O += P @ V : warp tile 32(m) x 64(n) ----
        {
            int m = wm*32;
            float f0 = RF[m + gid];
            float f1 = RF[m + gid + 8];
            float f2 = RF[m + 16 + gid];
            float f3 = RF[m + 16 + gid + 8];
            #pragma unroll
            for (int ni = 0; ni < 8; ni++) {
                oacc[0][ni][0] *= f0; oacc[0][ni][1] *= f0;
                oacc[0][ni][2] *= f1; oacc[0][ni][3] *= f1;
                oacc[1][ni][0] *= f2; oacc[1][ni][1] *= f2;
                oacc[1][ni][2] *= f3; oacc[1][ni][3] *= f3;
            }
        }
        #pragma unroll
        for (int ks = 0; ks < 4; ks++) {
            int kw = ks * 8;
            unsigned ah[2][4], al[2][4];
            #pragma unroll
            for (int mi = 0; mi < 2; mi++) {
                int m = wm*32 + mi*16;
                int o0 = (m + gid)     * 36 + kw + tig;
                int o1 = (m + gid + 8) * 36 + kw + tig;
                ah[mi][0] = PHW[o0];     ah[mi][1] = PHW[o1];
                ah[mi][2] = PHW[o0 + 4]; ah[mi][3] = PHW[o1 + 4];
                al[mi][0] = PLW[o0];     al[mi][1] = PLW[o1];
                al[mi][2] = PLW[o0 + 4]; al[mi][3] = PLW[o1 + 4];
            }
            #pragma unroll
            for (int ni = 0; ni < 8; ni++) {
                int n = wn*64 + ni*8;
                int ob = (n + gid) * 36 + kw + tig;
                unsigned bh0 = VHW[ob], bh1 = VHW[ob + 4];
                unsigned bl0 = VLW[ob], bl1 = VLW[ob + 4];
                #pragma unroll
                for (int mi = 0; mi < 2; mi++) {
                    float* d = oacc[mi][ni];
                    mma_bf16(d[0],d[1],d[2],d[3], ah[mi][0],ah[mi][1],ah[mi][2],ah[mi][3], bh0,bh1);
                    mma_bf16(d[0],d[1],d[2],d[3], al[mi][0],al[mi][1],al[mi][2],al[mi][3], bh0,bh1);
                    mma_bf16(d[0],d[1],d[2],d[3], ah[mi][0],ah[mi][1],ah[mi][2],ah[mi][3], bl0,bl1);
                }
            }
        }
    }

    __syncthreads();
    // ---- epilogue: divide by l, write g_O[b, q, h*128 + c] ----
    int b = bh >> 4;
    int h = bh & 15;
    {
        int m = wm*32;
        float i0 = 1.0f / RL[m + gid];
        float i1 = 1.0f / RL[m + gid + 8];
        float i2 = 1.0f / RL[m + 16 + gid];
        float i3 = 1.0f / RL[m + 16 + gid + 8];
        #pragma unroll
        for (int mi = 0; mi < 2; mi++) {
            float ia = (mi == 0) ? i0 : i2;
            float ib = (mi == 0) ? i1 : i3;
            int r0 = q0 + wm*32 + mi*16 + gid;
            #pragma unroll
            for (int ni = 0; ni < 8; ni++) {
                int col = h*HDIM + wn*64 + ni*8 + tig*2;
                float2 vlo = make_float2(oacc[mi][ni][0] * ia, oacc[mi][ni][1] * ia);
                float2 vhi = make_float2(oacc[mi][ni][2] * ib, oacc[mi][ni][3] * ib);
                *(float2*)&g_O[((size_t)(b*TT + r0))     * DD + col] = vlo;
                *(float2*)&g_O[((size_t)(b*TT + r0 + 8)) * DD + col] = vhi;
            }
        }
    }
}

// ---------------------------------------------------------------------------
extern "C" void kernel_launch(void* const* d_in, const int* in_sizes, int n_in,
                              void* d_out, int out_size) {
    (void)in_sizes; (void)n_in; (void)out_size;
    const float* x       = (const float*)d_in[0];
    const float* Wq      = (const float*)d_in[1];
    const float* bq      = (const float*)d_in[2];
    const float* Wk      = (const float*)d_in[3];
    const float* bk      = (const float*)d_in[4];
    // d_in[5]=Wvq, d_in[6]=bvq, d_in[7]=v_keys: dead (top_k over full axis)
    const float* v_embed = (const float*)d_in[8];
    const float* Wo      = (const float*)d_in[9];
    const float* bo      = (const float*)d_in[10];
    float* out = (float*)d_out;

    float *qp = nullptr, *kp = nullptr, *op = nullptr;
    cudaGetSymbolAddress((void**)&qp, g_Q);
    cudaGetSymbolAddress((void**)&kp, g_K);
    cudaGetSymbolAddress((void**)&op, g_O);

    compute_c_kernel<<<DD/256, 256>>>(v_embed);
    compute_v_kernel<<<(BB*TT*DD)/256, 256>>>(x);

    int gsmem = 2 * GS_STAGE;    // 81920
    cudaFuncSetAttribute(gemm_bf16_kernel<0>,
                         cudaFuncAttributeMaxDynamicSharedMemorySize, gsmem);
    cudaFuncSetAttribute(gemm_bf16_kernel<1>,
                         cudaFuncAttributeMaxDynamicSharedMemorySize, gsmem);

    dim3 gg(DD/128, MROWS/128);
    gemm_bf16_kernel<0><<<gg, 256, gsmem>>>(x, Wq, bq, qp);
    gemm_bf16_kernel<0><<<gg, 256, gsmem>>>(x, Wk, bk, kp);

    int fsmem = FO_END;          // 214528
    cudaFuncSetAttribute(flash_tc_kernel,
                         cudaFuncAttributeMaxDynamicSharedMemorySize, fsmem);
    flash_tc_kernel<<<dim3(16, BB*HH), 256, fsmem>>>();

    gemm_bf16_kernel<1><<<gg, 256, gsmem>>>(op, Wo, bo, out);
}

// round 5
// speedup vs baseline: 2.0997x; 1.1224x over previous
#include <cuda_runtime.h>
#include <cuda_bf16.h>
#include <math.h>
#include <cstdint>

#define BB   2
#define TT   2048
#define DD   2048
#define HH   16
#define HDIM 128
#define MROWS (BB*TT)   // 4096

// Scratch (device globals: allocation-free per harness rules)
__device__ float g_Q[(size_t)BB*HH*TT*HDIM];
__device__ float g_K[(size_t)BB*HH*TT*HDIM];
__device__ float g_V[(size_t)BB*HH*TT*HDIM];
__device__ float g_O[(size_t)MROWS*DD];
__device__ float g_c[DD];
// pre-split operand buffers (bf16 hi/lo)
__device__ __nv_bfloat16 g_Ah[(size_t)MROWS*DD];
__device__ __nv_bfloat16 g_Al[(size_t)MROWS*DD];
__device__ __nv_bfloat16 g_Bh[(size_t)DD*DD];
__device__ __nv_bfloat16 g_Bl[(size_t)DD*DD];

// ---------------------------------------------------------------------------
__device__ __forceinline__ uint32_t s2u(const void* p) {
    uint32_t a;
    asm("{ .reg .u64 t; cvta.to.shared.u64 t, %1; cvt.u32.u64 %0, t; }"
        : "=r"(a) : "l"(p));
    return a;
}

__device__ __forceinline__ void cp16(uint32_t dst, const void* src) {
    asm volatile("cp.async.cg.shared.global [%0], [%1], 16;"
                 :: "r"(dst), "l"(src) : "memory");
}
#define CP_COMMIT() asm volatile("cp.async.commit_group;" ::: "memory")
#define CP_WAIT1()  asm volatile("cp.async.wait_group 1;" ::: "memory")

// bf16 split: a = hi + lo, hi = truncate-to-bf16 (bit trunc), lo = rn(residual)
__device__ __forceinline__ void bsplit2(float a0, float a1, unsigned& h, unsigned& l) {
    unsigned u0 = __float_as_uint(a0), u1 = __float_as_uint(a1);
    asm("prmt.b32 %0, %1, %2, 0x7632;" : "=r"(h) : "r"(u0), "r"(u1));
    float l0 = a0 - __uint_as_float(u0 & 0xffff0000u);
    float l1 = a1 - __uint_as_float(u1 & 0xffff0000u);
    asm("cvt.rn.bf16x2.f32 %0, %1, %2;" : "=r"(l) : "f"(l1), "f"(l0));
}

__device__ __forceinline__ void mma_bf16(float& d0, float& d1, float& d2, float& d3,
                                         unsigned a0, unsigned a1, unsigned a2, unsigned a3,
                                         unsigned b0, unsigned b1) {
    asm volatile(
        "mma.sync.aligned.m16n8k16.row.col.f32.bf16.bf16.f32 "
        "{%0,%1,%2,%3}, {%4,%5,%6,%7}, {%8,%9}, {%0,%1,%2,%3};\n"
        : "+f"(d0), "+f"(d1), "+f"(d2), "+f"(d3)
        : "r"(a0), "r"(a1), "r"(a2), "r"(a3), "r"(b0), "r"(b1));
}

// ---------------------------------------------------------------------------
// c[d] = 2 * sum_{j<4} v_embed[j][d]   (top_k with k == NVK selects everything)
// ---------------------------------------------------------------------------
__global__ void compute_c_kernel(const float* __restrict__ v_embed) {
    int d = blockIdx.x * 256 + threadIdx.x;
    if (d < DD)
        g_c[d] = 2.0f * (v_embed[d] + v_embed[DD + d] + v_embed[2*DD + d] + v_embed[3*DD + d]);
}

// V[b,h,t,hd] = x[b,t,h*128+hd] * c[h*128+hd]
__global__ void compute_v_kernel(const float* __restrict__ x) {
    int idx  = blockIdx.x * 256 + threadIdx.x;
    int dcol = idx & (DD - 1);
    int bt   = idx >> 11;
    int b    = bt >> 11;
    int t    = bt & (TT - 1);
    int h    = dcol >> 7;
    int hd   = dcol & 127;
    g_V[((size_t)(b*HH + h)*TT + t)*HDIM + hd] = x[idx] * g_c[dcol];
}

// ---------------------------------------------------------------------------
// split f32 -> (hi trunc-bf16, lo rn-bf16) global arrays. 4 elems/thread.
// ---------------------------------------------------------------------------
__global__ void split_kernel(const float* __restrict__ in,
                             __nv_bfloat16* __restrict__ hi,
                             __nv_bfloat16* __restrict__ lo) {
    int i = (blockIdx.x * 256 + threadIdx.x) * 4;
    float4 v = *(const float4*)(in + i);
    unsigned h01, l01, h23, l23;
    bsplit2(v.x, v.y, h01, l01);
    bsplit2(v.z, v.w, h23, l23);
    *(uint2*)(hi + i) = make_uint2(h01, h23);
    *(uint2*)(lo + i) = make_uint2(l01, l23);
}

// ---------------------------------------------------------------------------
// NT GEMM, bf16 3-term, cp.async staged: C[4096,2048] = A*B^T + bias
// CTA 128x128, 128 thr = 4 warps of 64x64. KBLK=32, 2 stages.
// stage layout: AH[128][20w] AL BH BL  (10240B each, 40960B/stage)
// ---------------------------------------------------------------------------
#define G2_STAGE 40960
#define G2_SMEM  (2*G2_STAGE)

template<int MODE>
__global__ void __launch_bounds__(128, 2) gemm_v2_kernel(
    const __nv_bfloat16* __restrict__ Ah, const __nv_bfloat16* __restrict__ Al,
    const __nv_bfloat16* __restrict__ Bh, const __nv_bfloat16* __restrict__ Bl,
    const float* __restrict__ bias, float* __restrict__ C)
{
    extern __shared__ __align__(16) char sm[];
    uint32_t sb = s2u(sm);

    int tid  = threadIdx.x;
    int lane = tid & 31;
    int warp = tid >> 5;
    int wm   = warp >> 1;          // 0..1
    int wn   = warp & 1;           // 0..1
    int gid  = lane >> 2;
    int tig  = lane & 3;

    int row0 = blockIdx.y * 128;
    int col0 = blockIdx.x * 128;

    // staging map: thread -> (r8 = tid>>2 in 0..31, c = tid&3); rows r8+32i
    int r8 = tid >> 2;
    int c  = tid & 3;

    const __nv_bfloat16* pAh = Ah + (size_t)(row0 + r8) * DD + c * 8;
    const __nv_bfloat16* pAl = Al + (size_t)(row0 + r8) * DD + c * 8;
    const __nv_bfloat16* pBh = Bh + (size_t)(col0 + r8) * DD + c * 8;
    const __nv_bfloat16* pBl = Bl + (size_t)(col0 + r8) * DD + c * 8;
    // dst byte offset within array: row*80 + c*16
    uint32_t dof = (uint32_t)(r8 * 80 + c * 16);

    float acc[4][8][4];
    #pragma unroll
    for (int mi = 0; mi < 4; mi++)
        #pragma unroll
        for (int ni = 0; ni < 8; ni++)
            #pragma unroll
            for (int r = 0; r < 4; r++) acc[mi][ni][r] = 0.0f;

    const int NKB = DD / 32;   // 64

    // prolog: issue stages 0 and 1
    #pragma unroll
    for (int pk = 0; pk < 2; pk++) {
        uint32_t base = sb + pk * G2_STAGE;
        size_t ko = (size_t)pk * 32;
        #pragma unroll
        for (int i = 0; i < 4; i++) {
            uint32_t d = base + dof + i * 2560;     // 32 rows * 80B
            size_t   s = ko + (size_t)(32 * i) * DD;
            cp16(d,          pAh + s);
            cp16(d + 10240,  pAl + s);
            cp16(d + 20480,  pBh + s);
            cp16(d + 30720,  pBl + s);
        }
        CP_COMMIT();
    }

    #pragma unroll 1
    for (int kb = 0; kb < NKB; kb++) {
        CP_WAIT1();
        __syncthreads();

        unsigned* AHW = (unsigned*)(sm + (kb & 1) * G2_STAGE);
        unsigned* ALW = AHW + 2560;
        unsigned* BHW = AHW + 5120;
        unsigned* BLW = AHW + 7680;

        #pragma unroll
        for (int ks = 0; ks < 2; ks++) {
            int kw = ks * 8;
            unsigned ah[4][4], al[4][4];
            #pragma unroll
            for (int mi = 0; mi < 4; mi++) {
                int m = wm*64 + mi*16;
                int o0 = (m + gid)     * 20 + kw + tig;
                int o1 = (m + gid + 8) * 20 + kw + tig;
                ah[mi][0] = AHW[o0];     ah[mi][1] = AHW[o1];
                ah[mi][2] = AHW[o0 + 4]; ah[mi][3] = AHW[o1 + 4];
                al[mi][0] = ALW[o0];     al[mi][1] = ALW[o1];
                al[mi][2] = ALW[o0 + 4]; al[mi][3] = ALW[o1 + 4];
            }
            #pragma unroll
            for (int ni = 0; ni < 8; ni++) {
                int n = wn*64 + ni*8;
                int ob = (n + gid) * 20 + kw + tig;
                unsigned bh0 = BHW[ob], bh1 = BHW[ob + 4];
                unsigned bl0 = BLW[ob], bl1 = BLW[ob + 4];
                #pragma unroll
                for (int mi = 0; mi < 4; mi++) {
                    float* d = acc[mi][ni];
                    mma_bf16(d[0],d[1],d[2],d[3], ah[mi][0],ah[mi][1],ah[mi][2],ah[mi][3], bh0,bh1);
                    mma_bf16(d[0],d[1],d[2],d[3], al[mi][0],al[mi][1],al[mi][2],al[mi][3], bh0,bh1);
                    mma_bf16(d[0],d[1],d[2],d[3], ah[mi][0],ah[mi][1],ah[mi][2],ah[mi][3], bl0,bl1);
                }
            }
        }
        __syncthreads();

        if (kb + 2 < NKB) {
            uint32_t base = sb + (kb & 1) * G2_STAGE;
            size_t ko = (size_t)(kb + 2) * 32;
            #pragma unroll
            for (int i = 0; i < 4; i++) {
                uint32_t d = base + dof + i * 2560;
                size_t   s = ko + (size_t)(32 * i) * DD;
                cp16(d,          pAh + s);
                cp16(d + 10240,  pAl + s);
                cp16(d + 20480,  pBh + s);
                cp16(d + 30720,  pBl + s);
            }
        }
        CP_COMMIT();   // commit every iter (possibly empty) keeps group count aligned
    }

    // epilogue
    #pragma unroll
    for (int mi = 0; mi < 4; mi++) {
        #pragma unroll
        for (int ni = 0; ni < 8; ni++) {
            int colA = col0 + wn*64 + ni*8 + tig*2;
            #pragma unroll
            for (int r = 0; r < 4; r++) {
                int row = row0 + wm*64 + mi*16 + gid + ((r >> 1) ? 8 : 0);
                int col = colA + (r & 1);
                float v = acc[mi][ni][r] + bias[col];
                if (MODE == 0) {
                    int b = row >> 11, t = row & (TT - 1);
                    int h = col >> 7,  hd = col & 127;
                    C[((size_t)(b*HH + h)*TT + t)*HDIM + hd] = v;
                } else {
                    C[(size_t)row * DD + col] = v;
                }
            }
        }
    }
}

// ---------------------------------------------------------------------------
// Flash attention on tensor cores (bf16 3-term, mma.sync), causal. (R3, proven)
// ---------------------------------------------------------------------------
#define FO_QH 0
#define FO_QL (FO_QH + 128*68*4)
#define FO_KH (FO_QL + 128*68*4)
#define FO_KL (FO_KH + 64*68*4)
#define FO_VH (FO_KL + 64*68*4)
#define FO_VL (FO_VH + 128*36*4)
#define FO_SS (FO_VL + 128*36*4)
#define FO_PH (FO_SS + 128*68*4)
#define FO_PL (FO_PH + 128*36*4)
#define FO_RM (FO_PL + 128*36*4)
#define FO_RL (FO_RM + 128*4)
#define FO_RF (FO_RL + 128*4)
#define FO_END (FO_RF + 128*4)

__global__ void __launch_bounds__(256, 1) flash_tc_kernel() {
    extern __shared__ __align__(16) char fsm[];
    unsigned* QHW = (unsigned*)(fsm + FO_QH);
    unsigned* QLW = (unsigned*)(fsm + FO_QL);
    unsigned* KHW = (unsigned*)(fsm + FO_KH);
    unsigned* KLW = (unsigned*)(fsm + FO_KL);
    unsigned* VHW = (unsigned*)(fsm + FO_VH);
    unsigned* VLW = (unsigned*)(fsm + FO_VL);
    float*    SS  = (float*)   (fsm + FO_SS);
    unsigned* PHW = (unsigned*)(fsm + FO_PH);
    unsigned* PLW = (unsigned*)(fsm + FO_PL);
    float*    RM  = (float*)   (fsm + FO_RM);
    float*    RL  = (float*)   (fsm + FO_RL);
    float*    RF  = (float*)   (fsm + FO_RF);

    int tid  = threadIdx.x;
    int lane = tid & 31;
    int warp = tid >> 5;
    int wm   = warp >> 1;
    int wn   = warp & 1;
    int gid  = lane >> 2;
    int tig  = lane & 3;

    int qtile = 15 - blockIdx.x;
    int bh    = blockIdx.y;
    int q0    = qtile * 128;

    const float* Qg = g_Q + ((size_t)bh * TT + q0) * HDIM;
    const float* Kg = g_K + (size_t)bh * TT * HDIM;
    const float* Vg = g_V + (size_t)bh * TT * HDIM;

    {
        int r  = tid >> 1;
        int kq = (tid & 1) * 64;
        const float* src = Qg + (size_t)r * HDIM + kq;
        int wo = r*68 + kq/2;
        #pragma unroll
        for (int j = 0; j < 8; j++) {
            float4 v0 = *(const float4*)(src + 8*j);
            float4 v1 = *(const float4*)(src + 8*j + 4);
            unsigned h0,l0,h1,l1,h2,l2,h3,l3;
            bsplit2(v0.x, v0.y, h0, l0);
            bsplit2(v0.z, v0.w, h1, l1);
            bsplit2(v1.x, v1.y, h2, l2);
            bsplit2(v1.z, v1.w, h3, l3);
            *(uint4*)&QHW[wo + 4*j] = make_uint4(h0,h1,h2,h3);
            *(uint4*)&QLW[wo + 4*j] = make_uint4(l0,l1,l2,l3);
        }
    }
    if (tid < 128) { RM[tid] = -1e30f; RL[tid] = 0.0f; }

    float oacc[2][8][4];
    #pragma unroll
    for (int mi = 0; mi < 2; mi++)
        #pragma unroll
        for (int ni = 0; ni < 8; ni++)
            #pragma unroll
            for (int r = 0; r < 4; r++) oacc[mi][ni][r] = 0.0f;

    const float scale = 0.08838834764831845f;
    int nkt = 2*qtile + 2;

    for (int kt = 0; kt < nkt; kt++) {
        int k0 = kt * 64;
        __syncthreads();

        {
            int r  = tid >> 2;
            int kq = (tid & 3) * 32;
            const float* src = Kg + (size_t)(k0 + r) * HDIM + kq;
            int wo = r*68 + kq/2;
            #pragma unroll
            for (int j = 0; j < 4; j++) {
                float4 v0 = *(const float4*)(src + 8*j);
                float4 v1 = *(const float4*)(src + 8*j + 4);
                unsigned h0,l0,h1,l1,h2,l2,h3,l3;
                bsplit2(v0.x, v0.y, h0, l0);
                bsplit2(v0.z, v0.w, h1, l1);
                bsplit2(v1.x, v1.y, h2, l2);
                bsplit2(v1.z, v1.w, h3, l3);
                *(uint4*)&KHW[wo + 4*j] = make_uint4(h0,h1,h2,h3);
                *(uint4*)&KLW[wo + 4*j] = make_uint4(l0,l1,l2,l3);
            }
        }
        {
            int n = tid & 127;
            int tb = (tid >> 7) * 2;
            #pragma unroll
            for (int p = 0; p < 16; p++) {
                int t = p*4 + tb;
                float v0 = Vg[(size_t)(k0 + t)     * HDIM + n];
                float v1 = Vg[(size_t)(k0 + t + 1) * HDIM + n];
                unsigned h, l;
                bsplit2(v0, v1, h, l);
                VHW[n*36 + (t >> 1)] = h;
                VLW[n*36 + (t >> 1)] = l;
            }
        }
        __syncthreads();

        float sacc[2][4][4];
        #pragma unroll
        for (int mi = 0; mi < 2; mi++)
            #pragma unroll
            for (int ni = 0; ni < 4; ni++)
                #pragma unroll
                for (int r = 0; r < 4; r++) sacc[mi][ni][r] = 0.0f;

        #pragma unroll
        for (int ks = 0; ks < 8; ks++) {
            int kw = ks * 8;
            unsigned ah[2][4], al[2][4];
            #pragma unroll
            for (int mi = 0; mi < 2; mi++) {
                int m = wm*32 + mi*16;
                int o0 = (m + gid)     * 68 + kw + tig;
                int o1 = (m + gid + 8) * 68 + kw + tig;
                ah[mi][0] = QHW[o0];     ah[mi][1] = QHW[o1];
                ah[mi][2] = QHW[o0 + 4]; ah[mi][3] = QHW[o1 + 4];
                al[mi][0] = QLW[o0];     al[mi][1] = QLW[o1];
                al[mi][2] = QLW[o0 + 4]; al[mi][3] = QLW[o1 + 4];
            }
            #pragma unroll
            for (int ni = 0; ni < 4; ni++) {
                int n = wn*32 + ni*8;
                int ob = (n + gid) * 68 + kw + tig;
                unsigned bh0 = KHW[ob], bh1 = KHW[ob + 4];
                unsigned bl0 = KLW[ob], bl1 = KLW[ob + 4];
                #pragma unroll
                for (int mi = 0; mi < 2; mi++) {
                    float* d = sacc[mi][ni];
                    mma_bf16(d[0],d[1],d[2],d[3], ah[mi][0],ah[mi][1],ah[mi][2],ah[mi][3], bh0,bh1);
                    mma_bf16(d[0],d[1],d[2],d[3], al[mi][0],al[mi][1],al[mi][2],al[mi][3], bh0,bh1);
                    mma_bf16(d[0],d[1],d[2],d[3], ah[mi][0],ah[mi][1],ah[mi][2],ah[mi][3], bl0,bl1);
                }
            }
        }
        bool diag = (k0 + 63 > q0);
        #pragma unroll
        for (int mi = 0; mi < 2; mi++) {
            #pragma unroll
            for (int ni = 0; ni < 4; ni++) {
                #pragma unroll
                for (int r = 0; r < 4; r++) {
                    int row = wm*32 + mi*16 + gid + ((r >> 1) ? 8 : 0);
                    int col = wn*32 + ni*8 + tig*2 + (r & 1);
                    float sv = sacc[mi][ni][r] * scale;
                    if (diag && (k0 + col > q0 + row)) sv = -1e30f;
                    SS[row*68 + col] = sv;
                }
            }
        }
        __syncthreads();

        {
            int row = tid >> 1;
            int kq  = (tid & 1) * 32;
            float e[32];
            #pragma unroll
            for (int j = 0; j < 8; j++)
                *(float4*)&e[4*j] = *(const float4*)&SS[row*68 + kq + 4*j];
            float mx = -1e30f;
            #pragma unroll
            for (int j = 0; j < 32; j++) mx = fmaxf(mx, e[j]);
            mx = fmaxf(mx, __shfl_xor_sync(0xffffffffu, mx, 1));
            float old_m = RM[row];
            float new_m = fmaxf(old_m, mx);
            float s = 0.0f;
            #pragma unroll
            for (int j = 0; j < 32; j++) {
                e[j] = __expf(e[j] - new_m);
                s += e[j];
            }
            s += __shfl_xor_sync(0xffffffffu, s, 1);
            if ((tid & 1) == 0) {
                float fac = __expf(old_m - new_m);
                RF[row] = fac;
                RL[row] = RL[row] * fac + s;
                RM[row] = new_m;
            }
            int wo = row*36 + kq/2;
            #pragma unroll
            for (int j = 0; j < 16; j++) {
                unsigned h, l;
                bsplit2(e[2*j], e[2*j+1], h, l);
                PHW[wo + j] = h;
                PLW[wo + j] = l;
            }
        }
        __syncthreads();

        {
            int m = wm*32;
            float f0 = RF[m + gid];
            float f1 = RF[m + gid + 8];
            float f2 = RF[m + 16 + gid];
            float f3 = RF[m + 16 + gid + 8];
            #pragma unroll
            for (int ni = 0; ni < 8; ni++) {
                oacc[0][ni][0] *= f0; oacc[0][ni][1] *= f0;
                oacc[0][ni][2] *= f1; oacc[0][ni][3] *= f1;
                oacc[1][ni][0] *= f2; oacc[1][ni][1] *= f2;
                oacc[1][ni][2] *= f3; oacc[1][ni][3] *= f3;
            }
        }
        #pragma unroll
        for (int ks = 0; ks < 4; ks++) {
            int kw = ks * 8;
            unsigned ah[2][4], al[2][4];
            #pragma unroll
            for (int mi = 0; mi < 2; mi++) {
                int m = wm*32 + mi*16;
                int o0 = (m + gid)     * 36 + kw + tig;
                int o1 = (m + gid + 8) * 36 + kw + tig;
                ah[mi][0] = PHW[o0];     ah[mi][1] = PHW[o1];
                ah[mi][2] = PHW[o0 + 4]; ah[mi][3] = PHW[o1 + 4];
                al[mi][0] = PLW[o0];     al[mi][1] = PLW[o1];
                al[mi][2] = PLW[o0 + 4]; al[mi][3] = PLW[o1 + 4];
            }
            #pragma unroll
            for (int ni = 0; ni < 8; ni++) {
                int n = wn*64 + ni*8;
                int ob = (n + gid) * 36 + kw + tig;
                unsigned bh0 = VHW[ob], bh1 = VHW[ob + 4];
                unsigned bl0 = VLW[ob], bl1 = VLW[ob + 4];
                #pragma unroll
                for (int mi = 0; mi < 2; mi++) {
                    float* d = oacc[mi][ni];
                    mma_bf16(d[0],d[1],d[2],d[3], ah[mi][0],ah[mi][1],ah[mi][2],ah[mi][3], bh0,bh1);
                    mma_bf16(d[0],d[1],d[2],d[3], al[mi][0],al[mi][1],al[mi][2],al[mi][3], bh0,bh1);
                    mma_bf16(d[0],d[1],d[2],d[3], ah[mi][0],ah[mi][1],ah[mi][2],ah[mi][3], bl0,bl1);
                }
            }
        }
    }

    __syncthreads();
    int b = bh >> 4;
    int h = bh & 15;
    {
        int m = wm*32;
        float i0 = 1.0f / RL[m + gid];
        float i1 = 1.0f / RL[m + gid + 8];
        float i2 = 1.0f / RL[m + 16 + gid];
        float i3 = 1.0f / RL[m + 16 + gid + 8];
        #pragma unroll
        for (int mi = 0; mi < 2; mi++) {
            float ia = (mi == 0) ? i0 : i2;
            float ib = (mi == 0) ? i1 : i3;
            int r0 = q0 + wm*32 + mi*16 + gid;
            #pragma unroll
            for (int ni = 0; ni < 8; ni++) {
                int col = h*HDIM + wn*64 + ni*8 + tig*2;
                float2 vlo = make_float2(oacc[mi][ni][0] * ia, oacc[mi][ni][1] * ia);
                float2 vhi = make_float2(oacc[mi][ni][2] * ib, oacc[mi][ni][3] * ib);
                *(float2*)&g_O[((size_t)(b*TT + r0))     * DD + col] = vlo;
                *(float2*)&g_O[((size_t)(b*TT + r0 + 8)) * DD + col] = vhi;
            }
        }
    }
}

// ---------------------------------------------------------------------------
extern "C" void kernel_launch(void* const* d_in, const int* in_sizes, int n_in,
                              void* d_out, int out_size) {
    (void)in_sizes; (void)n_in; (void)out_size;
    const float* x       = (const float*)d_in[0];
    const float* Wq      = (const float*)d_in[1];
    const float* bq      = (const float*)d_in[2];
    const float* Wk      = (const float*)d_in[3];
    const float* bk      = (const float*)d_in[4];
    // d_in[5]=Wvq, d_in[6]=bvq, d_in[7]=v_keys: dead (top_k over full axis)
    const float* v_embed = (const float*)d_in[8];
    const float* Wo      = (const float*)d_in[9];
    const float* bo      = (const float*)d_in[10];
    float* out = (float*)d_out;

    float *qp = nullptr, *kp = nullptr, *op = nullptr;
    __nv_bfloat16 *ah, *al, *bh, *bl;
    cudaGetSymbolAddress((void**)&qp, g_Q);
    cudaGetSymbolAddress((void**)&kp, g_K);
    cudaGetSymbolAddress((void**)&op, g_O);
    cudaGetSymbolAddress((void**)&ah, g_Ah);
    cudaGetSymbolAddress((void**)&al, g_Al);
    cudaGetSymbolAddress((void**)&bh, g_Bh);
    cudaGetSymbolAddress((void**)&bl, g_Bl);

    compute_c_kernel<<<DD/256, 256>>>(v_embed);
    compute_v_kernel<<<(BB*TT*DD)/256, 256>>>(x);

    cudaFuncSetAttribute(gemm_v2_kernel<0>,
                         cudaFuncAttributeMaxDynamicSharedMemorySize, G2_SMEM);
    cudaFuncSetAttribute(gemm_v2_kernel<1>,
                         cudaFuncAttributeMaxDynamicSharedMemorySize, G2_SMEM);

    dim3 gg(DD/128, MROWS/128);

    // split x once (A for Q and K gemms)
    split_kernel<<<(MROWS*DD)/1024, 256>>>(x, ah, al);

    split_kernel<<<(DD*DD)/1024, 256>>>(Wq, bh, bl);
    gemm_v2_kernel<0><<<gg, 128, G2_SMEM>>>(ah, al, bh, bl, bq, qp);

    split_kernel<<<(DD*DD)/1024, 256>>>(Wk, bh, bl);
    gemm_v2_kernel<0><<<gg, 128, G2_SMEM>>>(ah, al, bh, bl, bk, kp);

    int fsmem = FO_END;
    cudaFuncSetAttribute(flash_tc_kernel,
                         cudaFuncAttributeMaxDynamicSharedMemorySize, fsmem);
    flash_tc_kernel<<<dim3(16, BB*HH), 256, fsmem>>>();

    // split O and Wo, final projection
    split_kernel<<<(MROWS*DD)/1024, 256>>>(op, ah, al);
    split_kernel<<<(DD*DD)/1024, 256>>>(Wo, bh, bl);
    gemm_v2_kernel<1><<<gg, 128, G2_SMEM>>>(ah, al, bh, bl, bo, out);
}

// round 6
// speedup vs baseline: 2.3977x; 1.1419x over previous
#include <cuda_runtime.h>
#include <cuda_bf16.h>
#include <math.h>
#include <cstdint>

#define BB   2
#define TT   2048
#define DD   2048
#define HH   16
#define HDIM 128
#define MROWS (BB*TT)   // 4096

// Scratch (device globals: allocation-free per harness rules)
__device__ float g_c[DD];
// pre-split bf16 hi/lo operands
__device__ __nv_bfloat16 g_Qh[(size_t)BB*HH*TT*HDIM];
__device__ __nv_bfloat16 g_Ql[(size_t)BB*HH*TT*HDIM];
__device__ __nv_bfloat16 g_Kh[(size_t)BB*HH*TT*HDIM];
__device__ __nv_bfloat16 g_Kl[(size_t)BB*HH*TT*HDIM];
__device__ __nv_bfloat16 g_Vth[(size_t)BB*HH*HDIM*TT];   // transposed [bh][hd][t]
__device__ __nv_bfloat16 g_Vtl[(size_t)BB*HH*HDIM*TT];
__device__ __nv_bfloat16 g_Ah[(size_t)MROWS*DD];          // GEMM A (x split, O split)
__device__ __nv_bfloat16 g_Al[(size_t)MROWS*DD];
__device__ __nv_bfloat16 g_Bh[(size_t)DD*DD];             // GEMM B (W split)
__device__ __nv_bfloat16 g_Bl[(size_t)DD*DD];

// ---------------------------------------------------------------------------
__device__ __forceinline__ uint32_t s2u(const void* p) {
    uint32_t a;
    asm("{ .reg .u64 t; cvta.to.shared.u64 t, %1; cvt.u32.u64 %0, t; }"
        : "=r"(a) : "l"(p));
    return a;
}
__device__ __forceinline__ void cp16(uint32_t dst, const void* src) {
    asm volatile("cp.async.cg.shared.global [%0], [%1], 16;"
                 :: "r"(dst), "l"(src) : "memory");
}
#define CP_COMMIT() asm volatile("cp.async.commit_group;" ::: "memory")
#define CP_WAIT0()  asm volatile("cp.async.wait_group 0;" ::: "memory")
#define CP_WAIT1()  asm volatile("cp.async.wait_group 1;" ::: "memory")

// bf16 split: a = hi + lo, hi = truncate-to-bf16 (bit trunc), lo = rn(residual)
__device__ __forceinline__ void bsplit2(float a0, float a1, unsigned& h, unsigned& l) {
    unsigned u0 = __float_as_uint(a0), u1 = __float_as_uint(a1);
    asm("prmt.b32 %0, %1, %2, 0x7632;" : "=r"(h) : "r"(u0), "r"(u1));
    float l0 = a0 - __uint_as_float(u0 & 0xffff0000u);
    float l1 = a1 - __uint_as_float(u1 & 0xffff0000u);
    asm("cvt.rn.bf16x2.f32 %0, %1, %2;" : "=r"(l) : "f"(l1), "f"(l0));
}

__device__ __forceinline__ void mma_bf16(float& d0, float& d1, float& d2, float& d3,
                                         unsigned a0, unsigned a1, unsigned a2, unsigned a3,
                                         unsigned b0, unsigned b1) {
    asm volatile(
        "mma.sync.aligned.m16n8k16.row.col.f32.bf16.bf16.f32 "
        "{%0,%1,%2,%3}, {%4,%5,%6,%7}, {%8,%9}, {%0,%1,%2,%3};\n"
        : "+f"(d0), "+f"(d1), "+f"(d2), "+f"(d3)
        : "r"(a0), "r"(a1), "r"(a2), "r"(a3), "r"(b0), "r"(b1));
}

// ---------------------------------------------------------------------------
// c[d] = 2 * sum_{j<4} v_embed[j][d]   (top_k with k == NVK selects everything)
// ---------------------------------------------------------------------------
__global__ void compute_c_kernel(const float* __restrict__ v_embed) {
    int d = blockIdx.x * 256 + threadIdx.x;
    if (d < DD)
        g_c[d] = 2.0f * (v_embed[d] + v_embed[DD + d] + v_embed[2*DD + d] + v_embed[3*DD + d]);
}

// ---------------------------------------------------------------------------
// V transposed + split: Vt[bh][hd][t] (hi/lo bf16) = x[b,t,h*128+hd] * c
// block = (hd tile 32) x (t tile 64) for one bh; smem transpose.
// ---------------------------------------------------------------------------
__global__ void __launch_bounds__(256) vt_split_kernel(const float* __restrict__ x) {
    __shared__ float S[32][65];
    int hd0 = blockIdx.x * 32;
    int t0  = blockIdx.y * 64;
    int bh  = blockIdx.z;
    int b = bh >> 4, h = bh & 15;
    int tid = threadIdx.x;

    #pragma unroll
    for (int i = 0; i < 2; i++) {
        int fi = tid * 2 + i;            // 0..511
        int t  = fi >> 3;
        int q  = fi & 7;
        float4 v = *(const float4*)&x[((size_t)(b*TT + t0 + t)) * DD + h*128 + hd0 + q*4];
        const float* cp = &g_c[h*128 + hd0 + q*4];
        S[q*4+0][t] = v.x * cp[0];
        S[q*4+1][t] = v.y * cp[1];
        S[q*4+2][t] = v.z * cp[2];
        S[q*4+3][t] = v.w * cp[3];
    }
    __syncthreads();

    int hd = tid >> 3;
    int ts = (tid & 7) * 8;
    float a0 = S[hd][ts+0], a1 = S[hd][ts+1], a2 = S[hd][ts+2], a3 = S[hd][ts+3];
    float a4 = S[hd][ts+4], a5 = S[hd][ts+5], a6 = S[hd][ts+6], a7 = S[hd][ts+7];
    unsigned h0,l0,h1,l1,h2,l2,h3,l3;
    bsplit2(a0, a1, h0, l0);
    bsplit2(a2, a3, h1, l1);
    bsplit2(a4, a5, h2, l2);
    bsplit2(a6, a7, h3, l3);
    size_t w = ((size_t)(bh*128 + hd0 + hd)) * (TT/2) + (size_t)(t0 + ts) / 2;
    *(uint4*)&((unsigned*)g_Vth)[w] = make_uint4(h0, h1, h2, h3);
    *(uint4*)&((unsigned*)g_Vtl)[w] = make_uint4(l0, l1, l2, l3);
}

// ---------------------------------------------------------------------------
// split f32 -> (hi trunc-bf16, lo rn-bf16) global arrays. 4 elems/thread.
// ---------------------------------------------------------------------------
__global__ void split_kernel(const float* __restrict__ in,
                             __nv_bfloat16* __restrict__ hi,
                             __nv_bfloat16* __restrict__ lo) {
    int i = (blockIdx.x * 256 + threadIdx.x) * 4;
    float4 v = *(const float4*)(in + i);
    unsigned h01, l01, h23, l23;
    bsplit2(v.x, v.y, h01, l01);
    bsplit2(v.z, v.w, h23, l23);
    *(uint2*)(hi + i) = make_uint2(h01, h23);
    *(uint2*)(lo + i) = make_uint2(l01, l23);
}

// ---------------------------------------------------------------------------
// NT GEMM, bf16 3-term, cp.async staged: C[4096,2048] = A*B^T + bias
// CTA 128x128, 128 thr = 4 warps of 64x64. KBLK=32, 2 stages.
// MODE 0: write pre-split bf16 hi/lo words to per-head layout [bh][t][hd]
// MODE 1: write f32 row-major
// ---------------------------------------------------------------------------
#define G2_STAGE 40960
#define G2_SMEM  (2*G2_STAGE)

template<int MODE>
__global__ void __launch_bounds__(128, 2) gemm_v2_kernel(
    const __nv_bfloat16* __restrict__ Ah, const __nv_bfloat16* __restrict__ Al,
    const __nv_bfloat16* __restrict__ Bh, const __nv_bfloat16* __restrict__ Bl,
    const float* __restrict__ bias, float* __restrict__ Cf,
    unsigned* __restrict__ Chi, unsigned* __restrict__ Clo)
{
    extern __shared__ __align__(16) char sm[];
    uint32_t sb = s2u(sm);

    int tid  = threadIdx.x;
    int lane = tid & 31;
    int warp = tid >> 5;
    int wm   = warp >> 1;
    int wn   = warp & 1;
    int gid  = lane >> 2;
    int tig  = lane & 3;

    int row0 = blockIdx.y * 128;
    int col0 = blockIdx.x * 128;

    int r8 = tid >> 2;
    int c  = tid & 3;

    const __nv_bfloat16* pAh = Ah + (size_t)(row0 + r8) * DD + c * 8;
    const __nv_bfloat16* pAl = Al + (size_t)(row0 + r8) * DD + c * 8;
    const __nv_bfloat16* pBh = Bh + (size_t)(col0 + r8) * DD + c * 8;
    const __nv_bfloat16* pBl = Bl + (size_t)(col0 + r8) * DD + c * 8;
    uint32_t dof = (uint32_t)(r8 * 80 + c * 16);

    float acc[4][8][4];
    #pragma unroll
    for (int mi = 0; mi < 4; mi++)
        #pragma unroll
        for (int ni = 0; ni < 8; ni++)
            #pragma unroll
            for (int r = 0; r < 4; r++) acc[mi][ni][r] = 0.0f;

    const int NKB = DD / 32;   // 64

    #pragma unroll
    for (int pk = 0; pk < 2; pk++) {
        uint32_t base = sb + pk * G2_STAGE;
        size_t ko = (size_t)pk * 32;
        #pragma unroll
        for (int i = 0; i < 4; i++) {
            uint32_t d = base + dof + i * 2560;
            size_t   s = ko + (size_t)(32 * i) * DD;
            cp16(d,          pAh + s);
            cp16(d + 10240,  pAl + s);
            cp16(d + 20480,  pBh + s);
            cp16(d + 30720,  pBl + s);
        }
        CP_COMMIT();
    }

    #pragma unroll 1
    for (int kb = 0; kb < NKB; kb++) {
        CP_WAIT1();
        __syncthreads();

        unsigned* AHW = (unsigned*)(sm + (kb & 1) * G2_STAGE);
        unsigned* ALW = AHW + 2560;
        unsigned* BHW = AHW + 5120;
        unsigned* BLW = AHW + 7680;

        #pragma unroll
        for (int ks = 0; ks < 2; ks++) {
            int kw = ks * 8;
            unsigned ah[4][4], al[4][4];
            #pragma unroll
            for (int mi = 0; mi < 4; mi++) {
                int m = wm*64 + mi*16;
                int o0 = (m + gid)     * 20 + kw + tig;
                int o1 = (m + gid + 8) * 20 + kw + tig;
                ah[mi][0] = AHW[o0];     ah[mi][1] = AHW[o1];
                ah[mi][2] = AHW[o0 + 4]; ah[mi][3] = AHW[o1 + 4];
                al[mi][0] = ALW[o0];     al[mi][1] = ALW[o1];
                al[mi][2] = ALW[o0 + 4]; al[mi][3] = ALW[o1 + 4];
            }
            #pragma unroll
            for (int ni = 0; ni < 8; ni++) {
                int n = wn*64 + ni*8;
                int ob = (n + gid) * 20 + kw + tig;
                unsigned bh0 = BHW[ob], bh1 = BHW[ob + 4];
                unsigned bl0 = BLW[ob], bl1 = BLW[ob + 4];
                #pragma unroll
                for (int mi = 0; mi < 4; mi++) {
                    float* d = acc[mi][ni];
                    mma_bf16(d[0],d[1],d[2],d[3], ah[mi][0],ah[mi][1],ah[mi][2],ah[mi][3], bh0,bh1);
                    mma_bf16(d[0],d[1],d[2],d[3], al[mi][0],al[mi][1],al[mi][2],al[mi][3], bh0,bh1);
                    mma_bf16(d[0],d[1],d[2],d[3], ah[mi][0],ah[mi][1],ah[mi][2],ah[mi][3], bl0,bl1);
                }
            }
        }
        __syncthreads();

        if (kb + 2 < NKB) {
            uint32_t base = sb + (kb & 1) * G2_STAGE;
            size_t ko = (size_t)(kb + 2) * 32;
            #pragma unroll
            for (int i = 0; i < 4; i++) {
                uint32_t d = base + dof + i * 2560;
                size_t   s = ko + (size_t)(32 * i) * DD;
                cp16(d,          pAh + s);
                cp16(d + 10240,  pAl + s);
                cp16(d + 20480,  pBh + s);
                cp16(d + 30720,  pBl + s);
            }
        }
        CP_COMMIT();
    }

    // epilogue
    #pragma unroll
    for (int mi = 0; mi < 4; mi++) {
        #pragma unroll
        for (int ni = 0; ni < 8; ni++) {
            int colA = col0 + wn*64 + ni*8 + tig*2;
            float b0 = bias[colA], b1 = bias[colA + 1];
            int rowa = row0 + wm*64 + mi*16 + gid;
            float v0 = acc[mi][ni][0] + b0, v1 = acc[mi][ni][1] + b1;
            float v2 = acc[mi][ni][2] + b0, v3 = acc[mi][ni][3] + b1;
            if (MODE == 0) {
                int hh = colA >> 7, hd = colA & 127;
                int bb = rowa >> 11;
                unsigned h, l;
                size_t w = ((size_t)(bb*HH + hh)*TT + (rowa & (TT-1)))*64 + (hd >> 1);
                bsplit2(v0, v1, h, l);
                Chi[w] = h; Clo[w] = l;
                w = ((size_t)(bb*HH + hh)*TT + ((rowa + 8) & (TT-1)))*64 + (hd >> 1);
                bsplit2(v2, v3, h, l);
                Chi[w] = h; Clo[w] = l;
            } else {
                *(float2*)&Cf[(size_t)rowa * DD + colA]       = make_float2(v0, v1);
                *(float2*)&Cf[(size_t)(rowa + 8) * DD + colA] = make_float2(v2, v3);
            }
        }
    }
}

// ---------------------------------------------------------------------------
// Flash attention v2: pre-split bf16 inputs, cp.async pipelined, causal.
// CTA 256 thr, qtile 128, ktile 64, HD 128. QK warps 4x2 (32x32), PV 4x2 (32x64).
// smem: QH/QL [128][68w]; KH/KL double [64][68w]; VH/VL single [128][36w];
//       SS f32 [128][68] (P bf16 hi/lo overlaid in-place); RM/RL/RF.
// ---------------------------------------------------------------------------
#define F2_QH  0
#define F2_QL  (F2_QH + 34816)
#define F2_K   (F2_QL + 34816)        // 2 stages x (KH 17408 + KL 17408)
#define F2_VH  (F2_K  + 69632)
#define F2_VL  (F2_VH + 18432)
#define F2_SS  (F2_VL + 18432)
#define F2_RM  (F2_SS + 34816)
#define F2_RL  (F2_RM + 512)
#define F2_RF  (F2_RL + 512)
#define F2_END (F2_RF + 512)

__global__ void __launch_bounds__(256, 1) flash_tc_kernel() {
    extern __shared__ __align__(16) char fsm[];
    uint32_t sb = s2u(fsm);

    unsigned* QHW = (unsigned*)(fsm + F2_QH);
    unsigned* QLW = (unsigned*)(fsm + F2_QL);
    unsigned* VHW = (unsigned*)(fsm + F2_VH);
    unsigned* VLW = (unsigned*)(fsm + F2_VL);
    float*    SS  = (float*)   (fsm + F2_SS);
    unsigned* SSW = (unsigned*)(fsm + F2_SS);
    float*    RM  = (float*)   (fsm + F2_RM);
    float*    RL  = (float*)   (fsm + F2_RL);
    float*    RF  = (float*)   (fsm + F2_RF);

    int tid  = threadIdx.x;
    int lane = tid & 31;
    int warp = tid >> 5;
    int wm   = warp >> 1;
    int wn   = warp & 1;
    int gid  = lane >> 2;
    int tig  = lane & 3;

    int qtile = 15 - blockIdx.x;      // heavy first
    int bh    = blockIdx.y;
    int q0    = qtile * 128;
    int nkt   = 2*qtile + 2;

    const __nv_bfloat16* Qhg = g_Qh + ((size_t)bh * TT + q0) * HDIM;
    const __nv_bfloat16* Qlg = g_Ql + ((size_t)bh * TT + q0) * HDIM;
    const __nv_bfloat16* Khg = g_Kh + (size_t)bh * TT * HDIM;
    const __nv_bfloat16* Klg = g_Kl + (size_t)bh * TT * HDIM;
    const __nv_bfloat16* Vhg = g_Vth + (size_t)bh * HDIM * TT;
    const __nv_bfloat16* Vlg = g_Vtl + (size_t)bh * HDIM * TT;

    // staging maps
    int qr = tid >> 1, qc0 = (tid & 1) * 8;     // Q: 128 rows x 16 chunks
    int kr = tid >> 2, kc0 = (tid & 3) * 4;     // K: 64 rows x 16 chunks
    int vr = tid >> 1, vc0 = (tid & 1) * 4;     // V: 128 rows x 8 chunks

    // ---- prolog: group1 = [Q, K(0), V(0)], group2 = [K(1)] ----
    {
        #pragma unroll
        for (int i = 0; i < 8; i++) {
            int ch = qc0 + i;
            uint32_t d = sb + F2_QH + (uint32_t)(qr * 272 + ch * 16);
            cp16(d,          Qhg + (size_t)qr * HDIM + ch * 8);
            cp16(d + 34816,  Qlg + (size_t)qr * HDIM + ch * 8);
        }
        #pragma unroll
        for (int i = 0; i < 4; i++) {
            int ch = kc0 + i;
            uint32_t d = sb + F2_K + (uint32_t)(kr * 272 + ch * 16);
            cp16(d,          Khg + (size_t)kr * HDIM + ch * 8);
            cp16(d + 17408,  Klg + (size_t)kr * HDIM + ch * 8);
        }
        #pragma unroll
        for (int i = 0; i < 4; i++) {
            int ch = vc0 + i;
            uint32_t d = sb + F2_VH + (uint32_t)(vr * 144 + ch * 16);
            cp16(d,          Vhg + (size_t)vr * TT + ch * 8);
            cp16(d + 18432,  Vlg + (size_t)vr * TT + ch * 8);
        }
        CP_COMMIT();
        if (nkt > 1) {
            #pragma unroll
            for (int i = 0; i < 4; i++) {
                int ch = kc0 + i;
                uint32_t d = sb + F2_K + 34816 + (uint32_t)(kr * 272 + ch * 16);
                cp16(d,          Khg + (size_t)(64 + kr) * HDIM + ch * 8);
                cp16(d + 17408,  Klg + (size_t)(64 + kr) * HDIM + ch * 8);
            }
        }
        CP_COMMIT();
    }

    if (tid < 128) { RM[tid] = -1e30f; RL[tid] = 0.0f; }

    float oacc[2][8][4];
    #pragma unroll
    for (int mi = 0; mi < 2; mi++)
        #pragma unroll
        for (int ni = 0; ni < 8; ni++)
            #pragma unroll
            for (int r = 0; r < 4; r++) oacc[mi][ni][r] = 0.0f;

    const float scale = 0.08838834764831845f;

    CP_WAIT1();            // group1 (Q, K0, V0) landed
    __syncthreads();

    for (int kt = 0; kt < nkt; kt++) {
        int k0 = kt * 64;
        unsigned* KHW = (unsigned*)(fsm + F2_K + (kt & 1) * 34816);
        unsigned* KLW = KHW + 4352;

        // ---- S = Q K^T ----
        float sacc[2][4][4];
        #pragma unroll
        for (int mi = 0; mi < 2; mi++)
            #pragma unroll
            for (int ni = 0; ni < 4; ni++)
                #pragma unroll
                for (int r = 0; r < 4; r++) sacc[mi][ni][r] = 0.0f;

        #pragma unroll
        for (int ks = 0; ks < 8; ks++) {
            int kw = ks * 8;
            unsigned ah[2][4], al[2][4];
            #pragma unroll
            for (int mi = 0; mi < 2; mi++) {
                int m = wm*32 + mi*16;
                int o0 = (m + gid)     * 68 + kw + tig;
                int o1 = (m + gid + 8) * 68 + kw + tig;
                ah[mi][0] = QHW[o0];     ah[mi][1] = QHW[o1];
                ah[mi][2] = QHW[o0 + 4]; ah[mi][3] = QHW[o1 + 4];
                al[mi][0] = QLW[o0];     al[mi][1] = QLW[o1];
                al[mi][2] = QLW[o0 + 4]; al[mi][3] = QLW[o1 + 4];
            }
            #pragma unroll
            for (int ni = 0; ni < 4; ni++) {
                int n = wn*32 + ni*8;
                int ob = (n + gid) * 68 + kw + tig;
                unsigned bh0 = KHW[ob], bh1 = KHW[ob + 4];
                unsigned bl0 = KLW[ob], bl1 = KLW[ob + 4];
                #pragma unroll
                for (int mi = 0; mi < 2; mi++) {
                    float* d = sacc[mi][ni];
                    mma_bf16(d[0],d[1],d[2],d[3], ah[mi][0],ah[mi][1],ah[mi][2],ah[mi][3], bh0,bh1);
                    mma_bf16(d[0],d[1],d[2],d[3], al[mi][0],al[mi][1],al[mi][2],al[mi][3], bh0,bh1);
                    mma_bf16(d[0],d[1],d[2],d[3], ah[mi][0],ah[mi][1],ah[mi][2],ah[mi][3], bl0,bl1);
                }
            }
        }
        bool diag = (k0 + 63 > q0);
        #pragma unroll
        for (int mi = 0; mi < 2; mi++) {
            #pragma unroll
            for (int ni = 0; ni < 4; ni++) {
                #pragma unroll
                for (int r = 0; r < 4; r++) {
                    int row = wm*32 + mi*16 + gid + ((r >> 1) ? 8 : 0);
                    int col = wn*32 + ni*8 + tig*2 + (r & 1);
                    float sv = sacc[mi][ni][r] * scale;
                    if (diag && (k0 + col > q0 + row)) sv = -1e30f;
                    SS[row*68 + col] = sv;
                }
            }
        }
        __syncthreads();                 // S ready; K buf kt&1 free

        // ---- prefetch K(kt+2) into freed buffer ----
        if (kt + 2 < nkt) {
            int kk0 = (kt + 2) * 64;
            #pragma unroll
            for (int i = 0; i < 4; i++) {
                int ch = kc0 + i;
                uint32_t d = sb + F2_K + (uint32_t)((kt & 1) * 34816 + kr * 272 + ch * 16);
                cp16(d,          Khg + (size_t)(kk0 + kr) * HDIM + ch * 8);
                cp16(d + 17408,  Klg + (size_t)(kk0 + kr) * HDIM + ch * 8);
            }
        }
        CP_COMMIT();

        // ---- online softmax; P (bf16 hi/lo) overlaid in-place over S ----
        {
            int row = tid >> 1;
            int hf  = tid & 1;
            int kq  = hf * 32;
            float e[32];
            #pragma unroll
            for (int j = 0; j < 8; j++)
                *(float4*)&e[4*j] = *(const float4*)&SS[row*68 + kq + 4*j];
            float mx = -1e30f;
            #pragma unroll
            for (int j = 0; j < 32; j++) mx = fmaxf(mx, e[j]);
            mx = fmaxf(mx, __shfl_xor_sync(0xffffffffu, mx, 1));
            float old_m = RM[row];
            float new_m = fmaxf(old_m, mx);
            float s = 0.0f;
            #pragma unroll
            for (int j = 0; j < 32; j++) {
                e[j] = __expf(e[j] - new_m);
                s += e[j];
            }
            s += __shfl_xor_sync(0xffffffffu, s, 1);
            if (hf == 0) {
                float fac = __expf(old_m - new_m);
                RF[row] = fac;
                RL[row] = RL[row] * fac + s;
                RM[row] = new_m;
            }
            // P: half hf writes exactly the words it read: [kq, kq+31]
            int pw = row*68 + kq;
            #pragma unroll
            for (int j = 0; j < 16; j++) {
                unsigned h, l;
                bsplit2(e[2*j], e[2*j+1], h, l);
                SSW[pw + j]      = h;
                SSW[pw + 16 + j] = l;
            }
        }
        CP_WAIT1();                      // V(kt) landed (K(kt+2) may be in flight)
        __syncthreads();                 // P ready + V visible

        // ---- O rescale + O += P @ V ----
        {
            int m = wm*32;
            float f0 = RF[m + gid];
            float f1 = RF[m + gid + 8];
            float f2 = RF[m + 16 + gid];
            float f3 = RF[m + 16 + gid + 8];
            #pragma unroll
            for (int ni = 0; ni < 8; ni++) {
                oacc[0][ni][0] *= f0; oacc[0][ni][1] *= f0;
                oacc[0][ni][2] *= f1; oacc[0][ni][3] *= f1;
                oacc[1][ni][0] *= f2; oacc[1][ni][1] *= f2;
                oacc[1][ni][2] *= f3; oacc[1][ni][3] *= f3;
            }
        }
        #pragma unroll
        for (int ks = 0; ks < 4; ks++) {
            int kw = ks * 8;
            int sh = (ks >= 2) ? 16 : 0;     // P overlay half-shift
            unsigned ah[2][4], al[2][4];
            #pragma unroll
            for (int mi = 0; mi < 2; mi++) {
                int m = wm*32 + mi*16;
                int o0 = (m + gid)     * 68 + kw + tig + sh;
                int o1 = (m + gid + 8) * 68 + kw + tig + sh;
                ah[mi][0] = SSW[o0];      ah[mi][1] = SSW[o1];
                ah[mi][2] = SSW[o0 + 4];  ah[mi][3] = SSW[o1 + 4];
                al[mi][0] = SSW[o0 + 16]; al[mi][1] = SSW[o1 + 16];
                al[mi][2] = SSW[o0 + 20]; al[mi][3] = SSW[o1 + 20];
            }
            #pragma unroll
            for (int ni = 0; ni < 8; ni++) {
                int n = wn*64 + ni*8;
                int ob = (n + gid) * 36 + kw + tig;
                unsigned bh0 = VHW[ob], bh1 = VHW[ob + 4];
                unsigned bl0 = VLW[ob], bl1 = VLW[ob + 4];
                #pragma unroll
                for (int mi = 0; mi < 2; mi++) {
                    float* d = oacc[mi][ni];
                    mma_bf16(d[0],d[1],d[2],d[3], ah[mi][0],ah[mi][1],ah[mi][2],ah[mi][3], bh0,bh1);
                    mma_bf16(d[0],d[1],d[2],d[3], al[mi][0],al[mi][1],al[mi][2],al[mi][3], bh0,bh1);
                    mma_bf16(d[0],d[1],d[2],d[3], ah[mi][0],ah[mi][1],ah[mi][2],ah[mi][3], bl0,bl1);
                }
            }
        }
        __syncthreads();                 // V buf free

        // ---- prefetch V(kt+1) ----
        if (kt + 1 < nkt) {
            int kk0 = (kt + 1) * 64;
            #pragma unroll
            for (int i = 0; i < 4; i++) {
                int ch = vc0 + i;
                uint32_t d = sb + F2_VH + (uint32_t)(vr * 144 + ch * 16);
                cp16(d,          Vhg + (size_t)vr * TT + kk0 + ch * 8);
                cp16(d + 18432,  Vlg + (size_t)vr * TT + kk0 + ch * 8);
            }
        }
        CP_COMMIT();
    }

    // ---- epilogue: O/l, write pre-split into GEMM A buffers ----
    int b = bh >> 4;
    int h = bh & 15;
    unsigned* AhW = (unsigned*)g_Ah;
    unsigned* AlW = (unsigned*)g_Al;
    {
        int m = wm*32;
        float i0 = 1.0f / RL[m + gid];
        float i1 = 1.0f / RL[m + gid + 8];
        float i2 = 1.0f / RL[m + 16 + gid];
        float i3 = 1.0f / RL[m + 16 + gid + 8];
        #pragma unroll
        for (int mi = 0; mi < 2; mi++) {
            float ia = (mi == 0) ? i0 : i2;
            float ib = (mi == 0) ? i1 : i3;
            int r0 = q0 + wm*32 + mi*16 + gid;
            #pragma unroll
            for (int ni = 0; ni < 8; ni++) {
                int col = h*HDIM + wn*64 + ni*8 + tig*2;
                unsigned hh, ll;
                size_t w = ((size_t)(b*TT + r0)) * (DD/2) + (col >> 1);
                bsplit2(oacc[mi][ni][0] * ia, oacc[mi][ni][1] * ia, hh, ll);
                AhW[w] = hh; AlW[w] = ll;
                w = ((size_t)(b*TT + r0 + 8)) * (DD/2) + (col >> 1);
                bsplit2(oacc[mi][ni][2] * ib, oacc[mi][ni][3] * ib, hh, ll);
                AhW[w] = hh; AlW[w] = ll;
            }
        }
    }
}

// ---------------------------------------------------------------------------
extern "C" void kernel_launch(void* const* d_in, const int* in_sizes, int n_in,
                              void* d_out, int out_size) {
    (void)in_sizes; (void)n_in; (void)out_size;
    const float* x       = (const float*)d_in[0];
    const float* Wq      = (const float*)d_in[1];
    const float* bq      = (const float*)d_in[2];
    const float* Wk      = (const float*)d_in[3];
    const float* bk      = (const float*)d_in[4];
    // d_in[5]=Wvq, d_in[6]=bvq, d_in[7]=v_keys: dead (top_k over full axis)
    const float* v_embed = (const float*)d_in[8];
    const float* Wo      = (const float*)d_in[9];
    const float* bo      = (const float*)d_in[10];
    float* out = (float*)d_out;

    __nv_bfloat16 *ah, *al, *bh, *bl, *qh, *ql, *kh, *kl;
    cudaGetSymbolAddress((void**)&ah, g_Ah);
    cudaGetSymbolAddress((void**)&al, g_Al);
    cudaGetSymbolAddress((void**)&bh, g_Bh);
    cudaGetSymbolAddress((void**)&bl, g_Bl);
    cudaGetSymbolAddress((void**)&qh, g_Qh);
    cudaGetSymbolAddress((void**)&ql, g_Ql);
    cudaGetSymbolAddress((void**)&kh, g_Kh);
    cudaGetSymbolAddress((void**)&kl, g_Kl);

    cudaFuncSetAttribute(gemm_v2_kernel<0>,
                         cudaFuncAttributeMaxDynamicSharedMemorySize, G2_SMEM);
    cudaFuncSetAttribute(gemm_v2_kernel<1>,
                         cudaFuncAttributeMaxDynamicSharedMemorySize, G2_SMEM);
    cudaFuncSetAttribute(flash_tc_kernel,
                         cudaFuncAttributeMaxDynamicSharedMemorySize, F2_END);

    dim3 gg(DD/128, MROWS/128);

    compute_c_kernel<<<DD/256, 256>>>(v_embed);
    vt_split_kernel<<<dim3(HDIM/32, TT/64, BB*HH), 256>>>(x);

    // split x once (A for Q and K gemms)
    split_kernel<<<(MROWS*DD)/1024, 256>>>(x, ah, al);

    split_kernel<<<(DD*DD)/1024, 256>>>(Wq, bh, bl);
    gemm_v2_kernel<0><<<gg, 128, G2_SMEM>>>(ah, al, bh, bl, bq, nullptr,
                                            (unsigned*)qh, (unsigned*)ql);

    split_kernel<<<(DD*DD)/1024, 256>>>(Wk, bh, bl);
    gemm_v2_kernel<0><<<gg, 128, G2_SMEM>>>(ah, al, bh, bl, bk, nullptr,
                                            (unsigned*)kh, (unsigned*)kl);

    flash_tc_kernel<<<dim3(16, BB*HH), 256, F2_END>>>();

    split_kernel<<<(DD*DD)/1024, 256>>>(Wo, bh, bl);
    gemm_v2_kernel<1><<<gg, 128, G2_SMEM>>>(ah, al, bh, bl, bo, out,
                                            nullptr, nullptr);
}

// round 7
// speedup vs baseline: 2.5931x; 1.0815x over previous
#include <cuda_runtime.h>
#include <cuda_bf16.h>
#include <math.h>
#include <cstdint>

#define BB   2
#define TT   2048
#define DD   2048
#define HH   16
#define HDIM 128
#define MROWS (BB*TT)   // 4096

// Scratch (device globals: allocation-free per harness rules)
__device__ float g_c[DD];
// pre-split bf16 hi/lo operands
__device__ __nv_bfloat16 g_Qh[(size_t)BB*HH*TT*HDIM];
__device__ __nv_bfloat16 g_Ql[(size_t)BB*HH*TT*HDIM];
__device__ __nv_bfloat16 g_Kh[(size_t)BB*HH*TT*HDIM];
__device__ __nv_bfloat16 g_Kl[(size_t)BB*HH*TT*HDIM];
__device__ __nv_bfloat16 g_Vth[(size_t)BB*HH*HDIM*TT];   // transposed [bh][hd][t]
__device__ __nv_bfloat16 g_Vtl[(size_t)BB*HH*HDIM*TT];
__device__ __nv_bfloat16 g_Ah[(size_t)MROWS*DD];          // GEMM A (x split, O split)
__device__ __nv_bfloat16 g_Al[(size_t)MROWS*DD];
__device__ __nv_bfloat16 g_Bh[(size_t)DD*DD];             // GEMM B (W split)
__device__ __nv_bfloat16 g_Bl[(size_t)DD*DD];

// ---------------------------------------------------------------------------
__device__ __forceinline__ uint32_t s2u(const void* p) {
    uint32_t a;
    asm("{ .reg .u64 t; cvta.to.shared.u64 t, %1; cvt.u32.u64 %0, t; }"
        : "=r"(a) : "l"(p));
    return a;
}
__device__ __forceinline__ void cp16(uint32_t dst, const void* src) {
    asm volatile("cp.async.cg.shared.global [%0], [%1], 16;"
                 :: "r"(dst), "l"(src) : "memory");
}
#define CP_COMMIT() asm volatile("cp.async.commit_group;" ::: "memory")
#define CP_WAIT1()  asm volatile("cp.async.wait_group 1;" ::: "memory")

__device__ __forceinline__ void ldsm4(unsigned r[4], uint32_t a) {
    asm volatile("ldmatrix.sync.aligned.m8n8.x4.shared.b16 {%0,%1,%2,%3}, [%4];"
                 : "=r"(r[0]), "=r"(r[1]), "=r"(r[2]), "=r"(r[3]) : "r"(a));
}
__device__ __forceinline__ void ldsm2(unsigned& r0, unsigned& r1, uint32_t a) {
    asm volatile("ldmatrix.sync.aligned.m8n8.x2.shared.b16 {%0,%1}, [%2];"
                 : "=r"(r0), "=r"(r1) : "r"(a));
}

// bf16 split: a = hi + lo, hi = truncate-to-bf16 (bit trunc), lo = rn(residual)
__device__ __forceinline__ void bsplit2(float a0, float a1, unsigned& h, unsigned& l) {
    unsigned u0 = __float_as_uint(a0), u1 = __float_as_uint(a1);
    asm("prmt.b32 %0, %1, %2, 0x7632;" : "=r"(h) : "r"(u0), "r"(u1));
    float l0 = a0 - __uint_as_float(u0 & 0xffff0000u);
    float l1 = a1 - __uint_as_float(u1 & 0xffff0000u);
    asm("cvt.rn.bf16x2.f32 %0, %1, %2;" : "=r"(l) : "f"(l1), "f"(l0));
}

__device__ __forceinline__ void mma_bf16(float& d0, float& d1, float& d2, float& d3,
                                         unsigned a0, unsigned a1, unsigned a2, unsigned a3,
                                         unsigned b0, unsigned b1) {
    asm volatile(
        "mma.sync.aligned.m16n8k16.row.col.f32.bf16.bf16.f32 "
        "{%0,%1,%2,%3}, {%4,%5,%6,%7}, {%8,%9}, {%0,%1,%2,%3};\n"
        : "+f"(d0), "+f"(d1), "+f"(d2), "+f"(d3)
        : "r"(a0), "r"(a1), "r"(a2), "r"(a3), "r"(b0), "r"(b1));
}

// ---------------------------------------------------------------------------
// c[d] = 2 * sum_{j<4} v_embed[j][d]   (top_k with k == NVK selects everything)
// ---------------------------------------------------------------------------
__global__ void compute_c_kernel(const float* __restrict__ v_embed) {
    int d = blockIdx.x * 256 + threadIdx.x;
    if (d < DD)
        g_c[d] = 2.0f * (v_embed[d] + v_embed[DD + d] + v_embed[2*DD + d] + v_embed[3*DD + d]);
}

// ---------------------------------------------------------------------------
// V transposed + split: Vt[bh][hd][t] (hi/lo bf16) = x[b,t,h*128+hd] * c
// ---------------------------------------------------------------------------
__global__ void __launch_bounds__(256) vt_split_kernel(const float* __restrict__ x) {
    __shared__ float S[32][65];
    int hd0 = blockIdx.x * 32;
    int t0  = blockIdx.y * 64;
    int bh  = blockIdx.z;
    int b = bh >> 4, h = bh & 15;
    int tid = threadIdx.x;

    #pragma unroll
    for (int i = 0; i < 2; i++) {
        int fi = tid * 2 + i;
        int t  = fi >> 3;
        int q  = fi & 7;
        float4 v = *(const float4*)&x[((size_t)(b*TT + t0 + t)) * DD + h*128 + hd0 + q*4];
        const float* cp = &g_c[h*128 + hd0 + q*4];
        S[q*4+0][t] = v.x * cp[0];
        S[q*4+1][t] = v.y * cp[1];
        S[q*4+2][t] = v.z * cp[2];
        S[q*4+3][t] = v.w * cp[3];
    }
    __syncthreads();

    int hd = tid >> 3;
    int ts = (tid & 7) * 8;
    float a0 = S[hd][ts+0], a1 = S[hd][ts+1], a2 = S[hd][ts+2], a3 = S[hd][ts+3];
    float a4 = S[hd][ts+4], a5 = S[hd][ts+5], a6 = S[hd][ts+6], a7 = S[hd][ts+7];
    unsigned h0,l0,h1,l1,h2,l2,h3,l3;
    bsplit2(a0, a1, h0, l0);
    bsplit2(a2, a3, h1, l1);
    bsplit2(a4, a5, h2, l2);
    bsplit2(a6, a7, h3, l3);
    size_t w = ((size_t)(bh*128 + hd0 + hd)) * (TT/2) + (size_t)(t0 + ts) / 2;
    *(uint4*)&((unsigned*)g_Vth)[w] = make_uint4(h0, h1, h2, h3);
    *(uint4*)&((unsigned*)g_Vtl)[w] = make_uint4(l0, l1, l2, l3);
}

// ---------------------------------------------------------------------------
// split f32 -> (hi trunc-bf16, lo rn-bf16) global arrays. 4 elems/thread.
// ---------------------------------------------------------------------------
__global__ void split_kernel(const float* __restrict__ in,
                             __nv_bfloat16* __restrict__ hi,
                             __nv_bfloat16* __restrict__ lo) {
    int i = (blockIdx.x * 256 + threadIdx.x) * 4;
    float4 v = *(const float4*)(in + i);
    unsigned h01, l01, h23, l23;
    bsplit2(v.x, v.y, h01, l01);
    bsplit2(v.z, v.w, h23, l23);
    *(uint2*)(hi + i) = make_uint2(h01, h23);
    *(uint2*)(lo + i) = make_uint2(l01, l23);
}

// ---------------------------------------------------------------------------
// NT GEMM, bf16 3-term, cp.async staged, LDSM fragments.
// CTA 128x128, 128 thr = 4 warps of 64x64. KBLK=32, 2 stages.
// stage: AH[128][20w] AL BH BL (10240B each)
// ---------------------------------------------------------------------------
#define G2_STAGE 40960
#define G2_SMEM  (2*G2_STAGE)

template<int MODE>
__global__ void __launch_bounds__(128, 2) gemm_v2_kernel(
    const __nv_bfloat16* __restrict__ Ah, const __nv_bfloat16* __restrict__ Al,
    const __nv_bfloat16* __restrict__ Bh, const __nv_bfloat16* __restrict__ Bl,
    const float* __restrict__ bias, float* __restrict__ Cf,
    unsigned* __restrict__ Chi, unsigned* __restrict__ Clo)
{
    extern __shared__ __align__(16) char sm[];
    uint32_t sb = s2u(sm);

    int tid  = threadIdx.x;
    int lane = tid & 31;
    int warp = tid >> 5;
    int wm   = warp >> 1;
    int wn   = warp & 1;
    int gid  = lane >> 2;
    int tig  = lane & 3;

    int row0 = blockIdx.y * 128;
    int col0 = blockIdx.x * 128;

    int r8 = tid >> 2;
    int c  = tid & 3;

    const __nv_bfloat16* pAh = Ah + (size_t)(row0 + r8) * DD + c * 8;
    const __nv_bfloat16* pAl = Al + (size_t)(row0 + r8) * DD + c * 8;
    const __nv_bfloat16* pBh = Bh + (size_t)(col0 + r8) * DD + c * 8;
    const __nv_bfloat16* pBl = Bl + (size_t)(col0 + r8) * DD + c * 8;
    uint32_t dof = (uint32_t)(r8 * 80 + c * 16);

    // LDSM lane address components
    int l7  = lane & 7;
    int l8  = (lane >> 3) & 1;
    int l16 = lane >> 4;
    // A: rows wm*64 + mi*16 + l7 + 8*l8, k-16B-sel l16
    uint32_t aLane = (uint32_t)((wm*64 + l7 + 8*l8) * 80) + (uint32_t)(l16 * 16);
    // B: rows wn*64 + ni*8 + (lane&7), k-16B-sel (lane>>3)&1
    uint32_t bLane = (uint32_t)((wn*64 + l7) * 80) + (uint32_t)(l8 * 16);

    float acc[4][8][4];
    #pragma unroll
    for (int mi = 0; mi < 4; mi++)
        #pragma unroll
        for (int ni = 0; ni < 8; ni++)
            #pragma unroll
            for (int r = 0; r < 4; r++) acc[mi][ni][r] = 0.0f;

    const int NKB = DD / 32;   // 64

    #pragma unroll
    for (int pk = 0; pk < 2; pk++) {
        uint32_t base = sb + pk * G2_STAGE;
        size_t ko = (size_t)pk * 32;
        #pragma unroll
        for (int i = 0; i < 4; i++) {
            uint32_t d = base + dof + i * 2560;
            size_t   s = ko + (size_t)(32 * i) * DD;
            cp16(d,          pAh + s);
            cp16(d + 10240,  pAl + s);
            cp16(d + 20480,  pBh + s);
            cp16(d + 30720,  pBl + s);
        }
        CP_COMMIT();
    }

    #pragma unroll 1
    for (int kb = 0; kb < NKB; kb++) {
        CP_WAIT1();
        __syncthreads();

        uint32_t stg = sb + (kb & 1) * G2_STAGE;

        #pragma unroll
        for (int ks = 0; ks < 2; ks++) {
            uint32_t kwB = (uint32_t)(ks * 32);   // 8 words
            unsigned ah[4][4], al[4][4];
            #pragma unroll
            for (int mi = 0; mi < 4; mi++) {
                uint32_t a = stg + aLane + kwB + (uint32_t)(mi * 1280);
                ldsm4(ah[mi], a);
                ldsm4(al[mi], a + 10240);
            }
            #pragma unroll
            for (int ni = 0; ni < 8; ni++) {
                uint32_t bAddr = stg + 20480 + bLane + kwB + (uint32_t)(ni * 640);
                unsigned bh0, bh1, bl0, bl1;
                ldsm2(bh0, bh1, bAddr);
                ldsm2(bl0, bl1, bAddr + 10240);
                #pragma unroll
                for (int mi = 0; mi < 4; mi++) {
                    float* d = acc[mi][ni];
                    mma_bf16(d[0],d[1],d[2],d[3], ah[mi][0],ah[mi][1],ah[mi][2],ah[mi][3], bh0,bh1);
                    mma_bf16(d[0],d[1],d[2],d[3], al[mi][0],al[mi][1],al[mi][2],al[mi][3], bh0,bh1);
                    mma_bf16(d[0],d[1],d[2],d[3], ah[mi][0],ah[mi][1],ah[mi][2],ah[mi][3], bl0,bl1);
                }
            }
        }
        __syncthreads();

        if (kb + 2 < NKB) {
            uint32_t base = sb + (kb & 1) * G2_STAGE;
            size_t ko = (size_t)(kb + 2) * 32;
            #pragma unroll
            for (int i = 0; i < 4; i++) {
                uint32_t d = base + dof + i * 2560;
                size_t   s = ko + (size_t)(32 * i) * DD;
                cp16(d,          pAh + s);
                cp16(d + 10240,  pAl + s);
                cp16(d + 20480,  pBh + s);
                cp16(d + 30720,  pBl + s);
            }
        }
        CP_COMMIT();
    }

    // epilogue
    #pragma unroll
    for (int mi = 0; mi < 4; mi++) {
        #pragma unroll
        for (int ni = 0; ni < 8; ni++) {
            int colA = col0 + wn*64 + ni*8 + tig*2;
            float b0 = bias[colA], b1 = bias[colA + 1];
            int rowa = row0 + wm*64 + mi*16 + gid;
            float v0 = acc[mi][ni][0] + b0, v1 = acc[mi][ni][1] + b1;
            float v2 = acc[mi][ni][2] + b0, v3 = acc[mi][ni][3] + b1;
            if (MODE == 0) {
                int hh = colA >> 7, hd = colA & 127;
                int bb = rowa >> 11;
                unsigned h, l;
                size_t w = ((size_t)(bb*HH + hh)*TT + (rowa & (TT-1)))*64 + (hd >> 1);
                bsplit2(v0, v1, h, l);
                Chi[w] = h; Clo[w] = l;
                w = ((size_t)(bb*HH + hh)*TT + ((rowa + 8) & (TT-1)))*64 + (hd >> 1);
                bsplit2(v2, v3, h, l);
                Chi[w] = h; Clo[w] = l;
            } else {
                *(float2*)&Cf[(size_t)rowa * DD + colA]       = make_float2(v0, v1);
                *(float2*)&Cf[(size_t)(rowa + 8) * DD + colA] = make_float2(v2, v3);
            }
        }
    }
}

// ---------------------------------------------------------------------------
// Flash attention v2 + LDSM: pre-split bf16 inputs, cp.async pipelined, causal.
// ---------------------------------------------------------------------------
#define F2_QH  0
#define F2_QL  (F2_QH + 34816)
#define F2_K   (F2_QL + 34816)        // 2 stages x (KH 17408 + KL 17408)
#define F2_VH  (F2_K  + 69632)
#define F2_VL  (F2_VH + 18432)
#define F2_SS  (F2_VL + 18432)
#define F2_RM  (F2_SS + 34816)
#define F2_RL  (F2_RM + 512)
#define F2_RF  (F2_RL + 512)
#define F2_END (F2_RF + 512)

__global__ void __launch_bounds__(256, 1) flash_tc_kernel() {
    extern __shared__ __align__(16) char fsm[];
    uint32_t sb = s2u(fsm);

    float*    SS  = (float*)   (fsm + F2_SS);
    unsigned* SSW = (unsigned*)(fsm + F2_SS);
    float*    RM  = (float*)   (fsm + F2_RM);
    float*    RL  = (float*)   (fsm + F2_RL);
    float*    RF  = (float*)   (fsm + F2_RF);

    int tid  = threadIdx.x;
    int lane = tid & 31;
    int warp = tid >> 5;
    int wm   = warp >> 1;
    int wn   = warp & 1;
    int gid  = lane >> 2;
    int tig  = lane & 3;

    int l7  = lane & 7;
    int l8  = (lane >> 3) & 1;
    int l16 = lane >> 4;

    int qtile = 15 - blockIdx.x;      // heavy first
    int bh    = blockIdx.y;
    int q0    = qtile * 128;
    int nkt   = 2*qtile + 2;

    const __nv_bfloat16* Qhg = g_Qh + ((size_t)bh * TT + q0) * HDIM;
    const __nv_bfloat16* Qlg = g_Ql + ((size_t)bh * TT + q0) * HDIM;
    const __nv_bfloat16* Khg = g_Kh + (size_t)bh * TT * HDIM;
    const __nv_bfloat16* Klg = g_Kl + (size_t)bh * TT * HDIM;
    const __nv_bfloat16* Vhg = g_Vth + (size_t)bh * HDIM * TT;
    const __nv_bfloat16* Vlg = g_Vtl + (size_t)bh * HDIM * TT;

    // staging maps
    int qr = tid >> 1, qc0 = (tid & 1) * 8;     // Q: 128 rows x 16 chunks
    int kr = tid >> 2, kc0 = (tid & 3) * 4;     // K: 64 rows x 16 chunks
    int vr = tid >> 1, vc0 = (tid & 1) * 4;     // V: 128 rows x 8 chunks

    // LDSM lane address bases (bytes)
    // Q/P (stride 272B): rows wm*32 + mi*16 + l7 + 8*l8
    uint32_t qLane = (uint32_t)((wm*32 + l7 + 8*l8) * 272) + (uint32_t)(l16 * 16);
    // K (stride 272B): rows wn*32 + ni*8 + l7
    uint32_t kLane = (uint32_t)((wn*32 + l7) * 272) + (uint32_t)(l8 * 16);
    // V (stride 144B): rows wn*64 + ni*8 + l7
    uint32_t vLane = (uint32_t)((wn*64 + l7) * 144) + (uint32_t)(l8 * 16);

    // ---- prolog: group1 = [Q, K(0), V(0)], group2 = [K(1)] ----
    {
        #pragma unroll
        for (int i = 0; i < 8; i++) {
            int ch = qc0 + i;
            uint32_t d = sb + F2_QH + (uint32_t)(qr * 272 + ch * 16);
            cp16(d,          Qhg + (size_t)qr * HDIM + ch * 8);
            cp16(d + 34816,  Qlg + (size_t)qr * HDIM + ch * 8);
        }
        #pragma unroll
        for (int i = 0; i < 4; i++) {
            int ch = kc0 + i;
            uint32_t d = sb + F2_K + (uint32_t)(kr * 272 + ch * 16);
            cp16(d,          Khg + (size_t)kr * HDIM + ch * 8);
            cp16(d + 17408,  Klg + (size_t)kr * HDIM + ch * 8);
        }
        #pragma unroll
        for (int i = 0; i < 4; i++) {
            int ch = vc0 + i;
            uint32_t d = sb + F2_VH + (uint32_t)(vr * 144 + ch * 16);
            cp16(d,          Vhg + (size_t)vr * TT + ch * 8);
            cp16(d + 18432,  Vlg + (size_t)vr * TT + ch * 8);
        }
        CP_COMMIT();
        if (nkt > 1) {
            #pragma unroll
            for (int i = 0; i < 4; i++) {
                int ch = kc0 + i;
                uint32_t d = sb + F2_K + 34816 + (uint32_t)(kr * 272 + ch * 16);
                cp16(d,          Khg + (size_t)(64 + kr) * HDIM + ch * 8);
                cp16(d + 17408,  Klg + (size_t)(64 + kr) * HDIM + ch * 8);
            }
        }
        CP_COMMIT();
    }

    if (tid < 128) { RM[tid] = -1e30f; RL[tid] = 0.0f; }

    float oacc[2][8][4];
    #pragma unroll
    for (int mi = 0; mi < 2; mi++)
        #pragma unroll
        for (int ni = 0; ni < 8; ni++)
            #pragma unroll
            for (int r = 0; r < 4; r++) oacc[mi][ni][r] = 0.0f;

    const float scale = 0.08838834764831845f;

    CP_WAIT1();            // group1 (Q, K0, V0) landed
    __syncthreads();

    for (int kt = 0; kt < nkt; kt++) {
        int k0 = kt * 64;
        uint32_t kBase = sb + F2_K + (uint32_t)((kt & 1) * 34816);

        // ---- S = Q K^T ----
        float sacc[2][4][4];
        #pragma unroll
        for (int mi = 0; mi < 2; mi++)
            #pragma unroll
            for (int ni = 0; ni < 4; ni++)
                #pragma unroll
                for (int r = 0; r < 4; r++) sacc[mi][ni][r] = 0.0f;

        #pragma unroll
        for (int ks = 0; ks < 8; ks++) {
            uint32_t kwB = (uint32_t)(ks * 32);
            unsigned ah[2][4], al[2][4];
            #pragma unroll
            for (int mi = 0; mi < 2; mi++) {
                uint32_t a = sb + F2_QH + qLane + kwB + (uint32_t)(mi * 16 * 272);
                ldsm4(ah[mi], a);
                ldsm4(al[mi], a + 34816);
            }
            #pragma unroll
            for (int ni = 0; ni < 4; ni++) {
                uint32_t bAddr = kBase + kLane + kwB + (uint32_t)(ni * 8 * 272);
                unsigned bh0, bh1, bl0, bl1;
                ldsm2(bh0, bh1, bAddr);
                ldsm2(bl0, bl1, bAddr + 17408);
                #pragma unroll
                for (int mi = 0; mi < 2; mi++) {
                    float* d = sacc[mi][ni];
                    mma_bf16(d[0],d[1],d[2],d[3], ah[mi][0],ah[mi][1],ah[mi][2],ah[mi][3], bh0,bh1);
                    mma_bf16(d[0],d[1],d[2],d[3], al[mi][0],al[mi][1],al[mi][2],al[mi][3], bh0,bh1);
                    mma_bf16(d[0],d[1],d[2],d[3], ah[mi][0],ah[mi][1],ah[mi][2],ah[mi][3], bl0,bl1);
                }
            }
        }
        bool diag = (k0 + 63 > q0);
        #pragma unroll
        for (int mi = 0; mi < 2; mi++) {
            #pragma unroll
            for (int ni = 0; ni < 4; ni++) {
                #pragma unroll
                for (int r = 0; r < 4; r++) {
                    int row = wm*32 + mi*16 + gid + ((r >> 1) ? 8 : 0);
                    int col = wn*32 + ni*8 + tig*2 + (r & 1);
                    float sv = sacc[mi][ni][r] * scale;
                    if (diag && (k0 + col > q0 + row)) sv = -1e30f;
                    SS[row*68 + col] = sv;
                }
            }
        }
        __syncthreads();                 // S ready; K buf kt&1 free

        // ---- prefetch K(kt+2) into freed buffer ----
        if (kt + 2 < nkt) {
            int kk0 = (kt + 2) * 64;
            #pragma unroll
            for (int i = 0; i < 4; i++) {
                int ch = kc0 + i;
                uint32_t d = sb + F2_K + (uint32_t)((kt & 1) * 34816 + kr * 272 + ch * 16);
                cp16(d,          Khg + (size_t)(kk0 + kr) * HDIM + ch * 8);
                cp16(d + 17408,  Klg + (size_t)(kk0 + kr) * HDIM + ch * 8);
            }
        }
        CP_COMMIT();

        // ---- online softmax; P (bf16 hi/lo) overlaid in-place over S ----
        {
            int row = tid >> 1;
            int hf  = tid & 1;
            int kq  = hf * 32;
            float e[32];
            #pragma unroll
            for (int j = 0; j < 8; j++)
                *(float4*)&e[4*j] = *(const float4*)&SS[row*68 + kq + 4*j];
            float mx = -1e30f;
            #pragma unroll
            for (int j = 0; j < 32; j++) mx = fmaxf(mx, e[j]);
            mx = fmaxf(mx, __shfl_xor_sync(0xffffffffu, mx, 1));
            float old_m = RM[row];
            float new_m = fmaxf(old_m, mx);
            float s = 0.0f;
            #pragma unroll
            for (int j = 0; j < 32; j++) {
                e[j] = __expf(e[j] - new_m);
                s += e[j];
            }
            s += __shfl_xor_sync(0xffffffffu, s, 1);
            if (hf == 0) {
                float fac = __expf(old_m - new_m);
                RF[row] = fac;
                RL[row] = RL[row] * fac + s;
                RM[row] = new_m;
            }
            int pw = row*68 + kq;
            #pragma unroll
            for (int j = 0; j < 16; j++) {
                unsigned h, l;
                bsplit2(e[2*j], e[2*j+1], h, l);
                SSW[pw + j]      = h;
                SSW[pw + 16 + j] = l;
            }
        }
        CP_WAIT1();                      // V(kt) landed (K(kt+2) may be in flight)
        __syncthreads();                 // P ready + V visible

        // ---- O rescale + O += P @ V ----
        {
            int m = wm*32;
            float f0 = RF[m + gid];
            float f1 = RF[m + gid + 8];
            float f2 = RF[m + 16 + gid];
            float f3 = RF[m + 16 + gid + 8];
            #pragma unroll
            for (int ni = 0; ni < 8; ni++) {
                oacc[0][ni][0] *= f0; oacc[0][ni][1] *= f0;
                oacc[0][ni][2] *= f1; oacc[0][ni][3] *= f1;
                oacc[1][ni][0] *= f2; oacc[1][ni][1] *= f2;
                oacc[1][ni][2] *= f3; oacc[1][ni][3] *= f3;
            }
        }
        #pragma unroll
        for (int ks = 0; ks < 4; ks++) {
            // P hi words for k16 chunk ks start at word ks*8 + (ks>=2 ? 16 : 0)
            uint32_t kwp = (uint32_t)((ks * 8 + ((ks >= 2) ? 16 : 0)) * 4);
            uint32_t kwv = (uint32_t)(ks * 32);
            unsigned ah[2][4], al[2][4];
            #pragma unroll
            for (int mi = 0; mi < 2; mi++) {
                uint32_t a = sb + F2_SS + qLane + kwp + (uint32_t)(mi * 16 * 272);
                ldsm4(ah[mi], a);
                ldsm4(al[mi], a + 64);        // lo overlay: +16 words
            }
            #pragma unroll
            for (int ni = 0; ni < 8; ni++) {
                uint32_t bAddr = sb + F2_VH + vLane + kwv + (uint32_t)(ni * 8 * 144);
                unsigned bh0, bh1, bl0, bl1;
                ldsm2(bh0, bh1, bAddr);
                ldsm2(bl0, bl1, bAddr + 18432);
                #pragma unroll
                for (int mi = 0; mi < 2; mi++) {
                    float* d = oacc[mi][ni];
                    mma_bf16(d[0],d[1],d[2],d[3], ah[mi][0],ah[mi][1],ah[mi][2],ah[mi][3], bh0,bh1);
                    mma_bf16(d[0],d[1],d[2],d[3], al[mi][0],al[mi][1],al[mi][2],al[mi][3], bh0,bh1);
                    mma_bf16(d[0],d[1],d[2],d[3], ah[mi][0],ah[mi][1],ah[mi][2],ah[mi][3], bl0,bl1);
                }
            }
        }
        __syncthreads();                 // V buf free

        // ---- prefetch V(kt+1) ----
        if (kt + 1 < nkt) {
            int kk0 = (kt + 1) * 64;
            #pragma unroll
            for (int i = 0; i < 4; i++) {
                int ch = vc0 + i;
                uint32_t d = sb + F2_VH + (uint32_t)(vr * 144 + ch * 16);
                cp16(d,          Vhg + (size_t)vr * TT + kk0 + ch * 8);
                cp16(d + 18432,  Vlg + (size_t)vr * TT + kk0 + ch * 8);
            }
        }
        CP_COMMIT();
    }

    // ---- epilogue: O/l, write pre-split into GEMM A buffers ----
    int b = bh >> 4;
    int h = bh & 15;
    unsigned* AhW = (unsigned*)g_Ah;
    unsigned* AlW = (unsigned*)g_Al;
    {
        int m = wm*32;
        float i0 = 1.0f / RL[m + gid];
        float i1 = 1.0f / RL[m + gid + 8];
        float i2 = 1.0f / RL[m + 16 + gid];
        float i3 = 1.0f / RL[m + 16 + gid + 8];
        #pragma unroll
        for (int mi = 0; mi < 2; mi++) {
            float ia = (mi == 0) ? i0 : i2;
            float ib = (mi == 0) ? i1 : i3;
            int r0 = q0 + wm*32 + mi*16 + gid;
            #pragma unroll
            for (int ni = 0; ni < 8; ni++) {
                int col = h*HDIM + wn*64 + ni*8 + tig*2;
                unsigned hh, ll;
                size_t w = ((size_t)(b*TT + r0)) * (DD/2) + (col >> 1);
                bsplit2(oacc[mi][ni][0] * ia, oacc[mi][ni][1] * ia, hh, ll);
                AhW[w] = hh; AlW[w] = ll;
                w = ((size_t)(b*TT + r0 + 8)) * (DD/2) + (col >> 1);
                bsplit2(oacc[mi][ni][2] * ib, oacc[mi][ni][3] * ib, hh, ll);
                AhW[w] = hh; AlW[w] = ll;
            }
        }
    }
}

// ---------------------------------------------------------------------------
extern "C" void kernel_launch(void* const* d_in, const int* in_sizes, int n_in,
                              void* d_out, int out_size) {
    (void)in_sizes; (void)n_in; (void)out_size;
    const float* x       = (const float*)d_in[0];
    const float* Wq      = (const float*)d_in[1];
    const float* bq      = (const float*)d_in[2];
    const float* Wk      = (const float*)d_in[3];
    const float* bk      = (const float*)d_in[4];
    // d_in[5]=Wvq, d_in[6]=bvq, d_in[7]=v_keys: dead (top_k over full axis)
    const float* v_embed = (const float*)d_in[8];
    const float* Wo      = (const float*)d_in[9];
    const float* bo      = (const float*)d_in[10];
    float* out = (float*)d_out;

    __nv_bfloat16 *ah, *al, *bh, *bl, *qh, *ql, *kh, *kl;
    cudaGetSymbolAddress((void**)&ah, g_Ah);
    cudaGetSymbolAddress((void**)&al, g_Al);
    cudaGetSymbolAddress((void**)&bh, g_Bh);
    cudaGetSymbolAddress((void**)&bl, g_Bl);
    cudaGetSymbolAddress((void**)&qh, g_Qh);
    cudaGetSymbolAddress((void**)&ql, g_Ql);
    cudaGetSymbolAddress((void**)&kh, g_Kh);
    cudaGetSymbolAddress((void**)&kl, g_Kl);

    cudaFuncSetAttribute(gemm_v2_kernel<0>,
                         cudaFuncAttributeMaxDynamicSharedMemorySize, G2_SMEM);
    cudaFuncSetAttribute(gemm_v2_kernel<1>,
                         cudaFuncAttributeMaxDynamicSharedMemorySize, G2_SMEM);
    cudaFuncSetAttribute(flash_tc_kernel,
                         cudaFuncAttributeMaxDynamicSharedMemorySize, F2_END);

    dim3 gg(DD/128, MROWS/128);

    compute_c_kernel<<<DD/256, 256>>>(v_embed);
    vt_split_kernel<<<dim3(HDIM/32, TT/64, BB*HH), 256>>>(x);

    // split x once (A for Q and K gemms)
    split_kernel<<<(MROWS*DD)/1024, 256>>>(x, ah, al);

    split_kernel<<<(DD*DD)/1024, 256>>>(Wq, bh, bl);
    gemm_v2_kernel<0><<<gg, 128, G2_SMEM>>>(ah, al, bh, bl, bq, nullptr,
                                            (unsigned*)qh, (unsigned*)ql);

    split_kernel<<<(DD*DD)/1024, 256>>>(Wk, bh, bl);
    gemm_v2_kernel<0><<<gg, 128, G2_SMEM>>>(ah, al, bh, bl, bk, nullptr,
                                            (unsigned*)kh, (unsigned*)kl);

    flash_tc_kernel<<<dim3(16, BB*HH), 256, F2_END>>>();

    split_kernel<<<(DD*DD)/1024, 256>>>(Wo, bh, bl);
    gemm_v2_kernel<1><<<gg, 128, G2_SMEM>>>(ah, al, bh, bl, bo, out,
                                            nullptr, nullptr);
}

// round 8
// speedup vs baseline: 2.7020x; 1.0420x over previous
#include <cuda_runtime.h>
#include <cuda_bf16.h>
#include <math.h>
#include <cstdint>

#define BB   2
#define TT   2048
#define DD   2048
#define HH   16
#define HDIM 128
#define MROWS (BB*TT)   // 4096

// Scratch (device globals: allocation-free per harness rules)
__device__ float g_c[DD];
// pre-split bf16 hi/lo operands
__device__ __nv_bfloat16 g_Qh[(size_t)BB*HH*TT*HDIM];
__device__ __nv_bfloat16 g_Ql[(size_t)BB*HH*TT*HDIM];
__device__ __nv_bfloat16 g_Kh[(size_t)BB*HH*TT*HDIM];
__device__ __nv_bfloat16 g_Kl[(size_t)BB*HH*TT*HDIM];
__device__ __nv_bfloat16 g_Vth[(size_t)BB*HH*HDIM*TT];   // transposed [bh][hd][t]
__device__ __nv_bfloat16 g_Vtl[(size_t)BB*HH*HDIM*TT];
__device__ __nv_bfloat16 g_Ah[(size_t)MROWS*DD];          // GEMM A (x split, O split)
__device__ __nv_bfloat16 g_Al[(size_t)MROWS*DD];
__device__ __nv_bfloat16 g_Bh[(size_t)DD*DD];             // GEMM B (Wq / Wo split)
__device__ __nv_bfloat16 g_Bl[(size_t)DD*DD];
__device__ __nv_bfloat16 g_B2h[(size_t)DD*DD];            // GEMM B2 (Wk split)
__device__ __nv_bfloat16 g_B2l[(size_t)DD*DD];

// ---------------------------------------------------------------------------
__device__ __forceinline__ uint32_t s2u(const void* p) {
    uint32_t a;
    asm("{ .reg .u64 t; cvta.to.shared.u64 t, %1; cvt.u32.u64 %0, t; }"
        : "=r"(a) : "l"(p));
    return a;
}
__device__ __forceinline__ void cp16(uint32_t dst, const void* src) {
    asm volatile("cp.async.cg.shared.global [%0], [%1], 16;"
                 :: "r"(dst), "l"(src) : "memory");
}
#define CP_COMMIT() asm volatile("cp.async.commit_group;" ::: "memory")
#define CP_WAIT0()  asm volatile("cp.async.wait_group 0;" ::: "memory")
#define CP_WAIT1()  asm volatile("cp.async.wait_group 1;" ::: "memory")

__device__ __forceinline__ void ldsm4(unsigned r[4], uint32_t a) {
    asm volatile("ldmatrix.sync.aligned.m8n8.x4.shared.b16 {%0,%1,%2,%3}, [%4];"
                 : "=r"(r[0]), "=r"(r[1]), "=r"(r[2]), "=r"(r[3]) : "r"(a));
}
__device__ __forceinline__ void ldsm2(unsigned& r0, unsigned& r1, uint32_t a) {
    asm volatile("ldmatrix.sync.aligned.m8n8.x2.shared.b16 {%0,%1}, [%2];"
                 : "=r"(r0), "=r"(r1) : "r"(a));
}

// bf16 split: a = hi + lo, hi = truncate-to-bf16 (bit trunc), lo = rn(residual)
__device__ __forceinline__ void bsplit2(float a0, float a1, unsigned& h, unsigned& l) {
    unsigned u0 = __float_as_uint(a0), u1 = __float_as_uint(a1);
    asm("prmt.b32 %0, %1, %2, 0x7632;" : "=r"(h) : "r"(u0), "r"(u1));
    float l0 = a0 - __uint_as_float(u0 & 0xffff0000u);
    float l1 = a1 - __uint_as_float(u1 & 0xffff0000u);
    asm("cvt.rn.bf16x2.f32 %0, %1, %2;" : "=r"(l) : "f"(l1), "f"(l0));
}

__device__ __forceinline__ void mma_bf16(float& d0, float& d1, float& d2, float& d3,
                                         unsigned a0, unsigned a1, unsigned a2, unsigned a3,
                                         unsigned b0, unsigned b1) {
    asm volatile(
        "mma.sync.aligned.m16n8k16.row.col.f32.bf16.bf16.f32 "
        "{%0,%1,%2,%3}, {%4,%5,%6,%7}, {%8,%9}, {%0,%1,%2,%3};\n"
        : "+f"(d0), "+f"(d1), "+f"(d2), "+f"(d3)
        : "r"(a0), "r"(a1), "r"(a2), "r"(a3), "r"(b0), "r"(b1));
}

// ---------------------------------------------------------------------------
// c[d] = 2 * sum_{j<4} v_embed[j][d]   (top_k with k == NVK selects everything)
// ---------------------------------------------------------------------------
__global__ void compute_c_kernel(const float* __restrict__ v_embed) {
    int d = blockIdx.x * 256 + threadIdx.x;
    if (d < DD)
        g_c[d] = 2.0f * (v_embed[d] + v_embed[DD + d] + v_embed[2*DD + d] + v_embed[3*DD + d]);
}

// ---------------------------------------------------------------------------
// V transposed + split: Vt[bh][hd][t] (hi/lo bf16) = x[b,t,h*128+hd] * c
// ---------------------------------------------------------------------------
__global__ void __launch_bounds__(256) vt_split_kernel(const float* __restrict__ x) {
    __shared__ float S[32][65];
    int hd0 = blockIdx.x * 32;
    int t0  = blockIdx.y * 64;
    int bh  = blockIdx.z;
    int b = bh >> 4, h = bh & 15;
    int tid = threadIdx.x;

    #pragma unroll
    for (int i = 0; i < 2; i++) {
        int fi = tid * 2 + i;
        int t  = fi >> 3;
        int q  = fi & 7;
        float4 v = *(const float4*)&x[((size_t)(b*TT + t0 + t)) * DD + h*128 + hd0 + q*4];
        const float* cp = &g_c[h*128 + hd0 + q*4];
        S[q*4+0][t] = v.x * cp[0];
        S[q*4+1][t] = v.y * cp[1];
        S[q*4+2][t] = v.z * cp[2];
        S[q*4+3][t] = v.w * cp[3];
    }
    __syncthreads();

    int hd = tid >> 3;
    int ts = (tid & 7) * 8;
    float a0 = S[hd][ts+0], a1 = S[hd][ts+1], a2 = S[hd][ts+2], a3 = S[hd][ts+3];
    float a4 = S[hd][ts+4], a5 = S[hd][ts+5], a6 = S[hd][ts+6], a7 = S[hd][ts+7];
    unsigned h0,l0,h1,l1,h2,l2,h3,l3;
    bsplit2(a0, a1, h0, l0);
    bsplit2(a2, a3, h1, l1);
    bsplit2(a4, a5, h2, l2);
    bsplit2(a6, a7, h3, l3);
    size_t w = ((size_t)(bh*128 + hd0 + hd)) * (TT/2) + (size_t)(t0 + ts) / 2;
    *(uint4*)&((unsigned*)g_Vth)[w] = make_uint4(h0, h1, h2, h3);
    *(uint4*)&((unsigned*)g_Vtl)[w] = make_uint4(l0, l1, l2, l3);
}

// ---------------------------------------------------------------------------
// split f32 -> (hi trunc-bf16, lo rn-bf16) global arrays. 4 elems/thread.
// ---------------------------------------------------------------------------
__global__ void split_kernel(const float* __restrict__ in,
                             __nv_bfloat16* __restrict__ hi,
                             __nv_bfloat16* __restrict__ lo) {
    int i = (blockIdx.x * 256 + threadIdx.x) * 4;
    float4 v = *(const float4*)(in + i);
    unsigned h01, l01, h23, l23;
    bsplit2(v.x, v.y, h01, l01);
    bsplit2(v.z, v.w, h23, l23);
    *(uint2*)(hi + i) = make_uint2(h01, h23);
    *(uint2*)(lo + i) = make_uint2(l01, l23);
}

// ---------------------------------------------------------------------------
// NT GEMM core, bf16 3-term, cp.async staged, LDSM fragments.
// CTA 128x128, 128 thr = 4 warps of 64x64. KBLK=32, 2 stages.
// ---------------------------------------------------------------------------
#define G2_STAGE 40960
#define G2_SMEM  (2*G2_STAGE)

template<int MODE>
__device__ __forceinline__ void gemm_body(
    const __nv_bfloat16* __restrict__ Ah, const __nv_bfloat16* __restrict__ Al,
    const __nv_bfloat16* __restrict__ Bh, const __nv_bfloat16* __restrict__ Bl,
    const float* __restrict__ bias, float* __restrict__ Cf,
    unsigned* __restrict__ Chi, unsigned* __restrict__ Clo, char* sm)
{
    uint32_t sb = s2u(sm);

    int tid  = threadIdx.x;
    int lane = tid & 31;
    int warp = tid >> 5;
    int wm   = warp >> 1;
    int wn   = warp & 1;
    int gid  = lane >> 2;
    int tig  = lane & 3;

    int row0 = blockIdx.y * 128;
    int col0 = blockIdx.x * 128;

    int r8 = tid >> 2;
    int c  = tid & 3;

    const __nv_bfloat16* pAh = Ah + (size_t)(row0 + r8) * DD + c * 8;
    const __nv_bfloat16* pAl = Al + (size_t)(row0 + r8) * DD + c * 8;
    const __nv_bfloat16* pBh = Bh + (size_t)(col0 + r8) * DD + c * 8;
    const __nv_bfloat16* pBl = Bl + (size_t)(col0 + r8) * DD + c * 8;
    uint32_t dof = (uint32_t)(r8 * 80 + c * 16);

    int l7  = lane & 7;
    int l8  = (lane >> 3) & 1;
    int l16 = lane >> 4;
    uint32_t aLane = (uint32_t)((wm*64 + l7 + 8*l8) * 80) + (uint32_t)(l16 * 16);
    uint32_t bLane = (uint32_t)((wn*64 + l7) * 80) + (uint32_t)(l8 * 16);

    float acc[4][8][4];
    #pragma unroll
    for (int mi = 0; mi < 4; mi++)
        #pragma unroll
        for (int ni = 0; ni < 8; ni++)
            #pragma unroll
            for (int r = 0; r < 4; r++) acc[mi][ni][r] = 0.0f;

    const int NKB = DD / 32;   // 64

    #pragma unroll
    for (int pk = 0; pk < 2; pk++) {
        uint32_t base = sb + pk * G2_STAGE;
        size_t ko = (size_t)pk * 32;
        #pragma unroll
        for (int i = 0; i < 4; i++) {
            uint32_t d = base + dof + i * 2560;
            size_t   s = ko + (size_t)(32 * i) * DD;
            cp16(d,          pAh + s);
            cp16(d + 10240,  pAl + s);
            cp16(d + 20480,  pBh + s);
            cp16(d + 30720,  pBl + s);
        }
        CP_COMMIT();
    }

    #pragma unroll 1
    for (int kb = 0; kb < NKB; kb++) {
        CP_WAIT1();
        __syncthreads();

        uint32_t stg = sb + (kb & 1) * G2_STAGE;

        #pragma unroll
        for (int ks = 0; ks < 2; ks++) {
            uint32_t kwB = (uint32_t)(ks * 32);
            unsigned ah[4][4], al[4][4];
            #pragma unroll
            for (int mi = 0; mi < 4; mi++) {
                uint32_t a = stg + aLane + kwB + (uint32_t)(mi * 1280);
                ldsm4(ah[mi], a);
                ldsm4(al[mi], a + 10240);
            }
            #pragma unroll
            for (int ni = 0; ni < 8; ni++) {
                uint32_t bAddr = stg + 20480 + bLane + kwB + (uint32_t)(ni * 640);
                unsigned bh0, bh1, bl0, bl1;
                ldsm2(bh0, bh1, bAddr);
                ldsm2(bl0, bl1, bAddr + 10240);
                #pragma unroll
                for (int mi = 0; mi < 4; mi++) {
                    float* d = acc[mi][ni];
                    mma_bf16(d[0],d[1],d[2],d[3], ah[mi][0],ah[mi][1],ah[mi][2],ah[mi][3], bh0,bh1);
                    mma_bf16(d[0],d[1],d[2],d[3], al[mi][0],al[mi][1],al[mi][2],al[mi][3], bh0,bh1);
                    mma_bf16(d[0],d[1],d[2],d[3], ah[mi][0],ah[mi][1],ah[mi][2],ah[mi][3], bl0,bl1);
                }
            }
        }
        __syncthreads();

        if (kb + 2 < NKB) {
            uint32_t base = sb + (kb & 1) * G2_STAGE;
            size_t ko = (size_t)(kb + 2) * 32;
            #pragma unroll
            for (int i = 0; i < 4; i++) {
                uint32_t d = base + dof + i * 2560;
                size_t   s = ko + (size_t)(32 * i) * DD;
                cp16(d,          pAh + s);
                cp16(d + 10240,  pAl + s);
                cp16(d + 20480,  pBh + s);
                cp16(d + 30720,  pBl + s);
            }
        }
        CP_COMMIT();
    }

    #pragma unroll
    for (int mi = 0; mi < 4; mi++) {
        #pragma unroll
        for (int ni = 0; ni < 8; ni++) {
            int colA = col0 + wn*64 + ni*8 + tig*2;
            float b0 = bias[colA], b1 = bias[colA + 1];
            int rowa = row0 + wm*64 + mi*16 + gid;
            float v0 = acc[mi][ni][0] + b0, v1 = acc[mi][ni][1] + b1;
            float v2 = acc[mi][ni][2] + b0, v3 = acc[mi][ni][3] + b1;
            if (MODE == 0) {
                int hh = colA >> 7, hd = colA & 127;
                int bb = rowa >> 11;
                unsigned h, l;
                size_t w = ((size_t)(bb*HH + hh)*TT + (rowa & (TT-1)))*64 + (hd >> 1);
                bsplit2(v0, v1, h, l);
                Chi[w] = h; Clo[w] = l;
                w = ((size_t)(bb*HH + hh)*TT + ((rowa + 8) & (TT-1)))*64 + (hd >> 1);
                bsplit2(v2, v3, h, l);
                Chi[w] = h; Clo[w] = l;
            } else {
                *(float2*)&Cf[(size_t)rowa * DD + colA]       = make_float2(v0, v1);
                *(float2*)&Cf[(size_t)(rowa + 8) * DD + colA] = make_float2(v2, v3);
            }
        }
    }
}

// fused Q+K projection: blockIdx.z selects weight/bias/output set
__global__ void __launch_bounds__(128, 2) gemm_qk_kernel(
    const __nv_bfloat16* Ah, const __nv_bfloat16* Al,
    const __nv_bfloat16* B1h, const __nv_bfloat16* B1l,
    const float* b1, unsigned* C1h, unsigned* C1l,
    const __nv_bfloat16* B2h, const __nv_bfloat16* B2l,
    const float* b2, unsigned* C2h, unsigned* C2l)
{
    extern __shared__ __align__(16) char sm[];
    bool z = (blockIdx.z != 0);
    gemm_body<0>(Ah, Al, z ? B2h : B1h, z ? B2l : B1l, z ? b2 : b1,
                 nullptr, z ? C2h : C1h, z ? C2l : C1l, sm);
}

__global__ void __launch_bounds__(128, 2) gemm_out_kernel(
    const __nv_bfloat16* Ah, const __nv_bfloat16* Al,
    const __nv_bfloat16* Bh, const __nv_bfloat16* Bl,
    const float* bias, float* Cf)
{
    extern __shared__ __align__(16) char sm[];
    gemm_body<1>(Ah, Al, Bh, Bl, bias, Cf, nullptr, nullptr, sm);
}

// ---------------------------------------------------------------------------
// Flash attention v3: FA2-style register-resident softmax, causal.
// 256 thr = 8 warps, each owns 16 q-rows. QK warp tile 16x64, PV 16x128.
// K and V double-buffered (cp.async depth 1), ONE sync per k-tile.
// smem: QH/QL [128][68w]; K 2 stages x (KH+KL [64][68w]); V 2 stages x (VH+VL [128][36w])
// ---------------------------------------------------------------------------
#define F3_QH   0
#define F3_QL   34816
#define F3_K    69632        // + stage*34816 ; KL at +17408
#define F3_V    139264       // + stage*36864 ; VL at +18432
#define F3_END  212992

__global__ void __launch_bounds__(256, 1) flash_v3_kernel() {
    extern __shared__ __align__(16) char fsm[];
    uint32_t sb = s2u(fsm);

    int tid  = threadIdx.x;
    int lane = tid & 31;
    int warp = tid >> 5;
    int gid  = lane >> 2;
    int tig  = lane & 3;
    int l7   = lane & 7;
    int l8   = (lane >> 3) & 1;
    int l16  = lane >> 4;

    int qtile = 15 - blockIdx.x;      // heavy first
    int bh    = blockIdx.y;
    int q0    = qtile * 128;
    int nkt   = 2*qtile + 2;

    const __nv_bfloat16* Qhg = g_Qh + ((size_t)bh * TT + q0) * HDIM;
    const __nv_bfloat16* Qlg = g_Ql + ((size_t)bh * TT + q0) * HDIM;
    const __nv_bfloat16* Khg = g_Kh + (size_t)bh * TT * HDIM;
    const __nv_bfloat16* Klg = g_Kl + (size_t)bh * TT * HDIM;
    const __nv_bfloat16* Vhg = g_Vth + (size_t)bh * HDIM * TT;
    const __nv_bfloat16* Vlg = g_Vtl + (size_t)bh * HDIM * TT;

    // staging maps
    int qr = tid >> 1, qc0 = (tid & 1) * 8;     // Q: 128 rows x 16 chunks
    int kr = tid >> 2, kc0 = (tid & 3) * 4;     // K: 64 rows x 16 chunks
    int vr = tid >> 1, vc0 = (tid & 1) * 4;     // V: 128 rows x 8 chunks

    // LDSM lane bases
    uint32_t qLane = (uint32_t)((warp*16 + l7 + 8*l8) * 272) + (uint32_t)(l16 * 16);
    uint32_t kLane = (uint32_t)(l7 * 272) + (uint32_t)(l8 * 16);
    uint32_t vLane = (uint32_t)(l7 * 144) + (uint32_t)(l8 * 16);

    // ---- prolog: group0 = [Q, K(0), V(0)] ----
    {
        #pragma unroll
        for (int i = 0; i < 8; i++) {
            int ch = qc0 + i;
            uint32_t d = sb + F3_QH + (uint32_t)(qr * 272 + ch * 16);
            cp16(d,          Qhg + (size_t)qr * HDIM + ch * 8);
            cp16(d + 34816,  Qlg + (size_t)qr * HDIM + ch * 8);
        }
        #pragma unroll
        for (int i = 0; i < 4; i++) {
            int ch = kc0 + i;
            uint32_t d = sb + F3_K + (uint32_t)(kr * 272 + ch * 16);
            cp16(d,          Khg + (size_t)kr * HDIM + ch * 8);
            cp16(d + 17408,  Klg + (size_t)kr * HDIM + ch * 8);
        }
        #pragma unroll
        for (int i = 0; i < 4; i++) {
            int ch = vc0 + i;
            uint32_t d = sb + F3_V + (uint32_t)(vr * 144 + ch * 16);
            cp16(d,          Vhg + (size_t)vr * TT + ch * 8);
            cp16(d + 18432,  Vlg + (size_t)vr * TT + ch * 8);
        }
        CP_COMMIT();
    }

    float oacc[16][4];
    #pragma unroll
    for (int ni = 0; ni < 16; ni++)
        #pragma unroll
        for (int r = 0; r < 4; r++) oacc[ni][r] = 0.0f;

    float rm0 = -1e30f, rm1 = -1e30f, rl0 = 0.0f, rl1 = 0.0f;
    const float scale = 0.08838834764831845f;   // 1/sqrt(128)
    int rowg0 = q0 + warp*16 + gid;             // lane's first q row (second = +8)

    #pragma unroll 1
    for (int kt = 0; kt < nkt; kt++) {
        int k0 = kt * 64;
        CP_WAIT0();
        __syncthreads();

        // prefetch K/V (kt+1) into the other buffer (read kt-1 finished at sync)
        if (kt + 1 < nkt) {
            int kk0 = (kt + 1) * 64;
            uint32_t ks_ = (uint32_t)(((kt + 1) & 1) * 34816);
            uint32_t vs_ = (uint32_t)(((kt + 1) & 1) * 36864);
            #pragma unroll
            for (int i = 0; i < 4; i++) {
                int ch = kc0 + i;
                uint32_t d = sb + F3_K + ks_ + (uint32_t)(kr * 272 + ch * 16);
                cp16(d,          Khg + (size_t)(kk0 + kr) * HDIM + ch * 8);
                cp16(d + 17408,  Klg + (size_t)(kk0 + kr) * HDIM + ch * 8);
            }
            #pragma unroll
            for (int i = 0; i < 4; i++) {
                int ch = vc0 + i;
                uint32_t d = sb + F3_V + vs_ + (uint32_t)(vr * 144 + ch * 16);
                cp16(d,          Vhg + (size_t)vr * TT + kk0 + ch * 8);
                cp16(d + 18432,  Vlg + (size_t)vr * TT + kk0 + ch * 8);
            }
        }
        CP_COMMIT();

        uint32_t kBase = sb + F3_K + (uint32_t)((kt & 1) * 34816);
        uint32_t vBase = sb + F3_V + (uint32_t)((kt & 1) * 36864);

        // ---- S = Q K^T : warp tile 16 x 64 ----
        float sacc[8][4];
        #pragma unroll
        for (int ni = 0; ni < 8; ni++)
            #pragma unroll
            for (int r = 0; r < 4; r++) sacc[ni][r] = 0.0f;

        #pragma unroll
        for (int ks = 0; ks < 8; ks++) {
            uint32_t kwB = (uint32_t)(ks * 32);
            unsigned qh4[4], ql4[4];
            uint32_t a = sb + F3_QH + qLane + kwB;
            ldsm4(qh4, a);
            ldsm4(ql4, a + 34816);
            #pragma unroll
            for (int ni = 0; ni < 8; ni++) {
                uint32_t ba = kBase + kLane + kwB + (uint32_t)(ni * 2176);
                unsigned kh0, kh1, kl0, kl1;
                ldsm2(kh0, kh1, ba);
                ldsm2(kl0, kl1, ba + 17408);
                float* d = sacc[ni];
                mma_bf16(d[0],d[1],d[2],d[3], qh4[0],qh4[1],qh4[2],qh4[3], kh0,kh1);
                mma_bf16(d[0],d[1],d[2],d[3], ql4[0],ql4[1],ql4[2],ql4[3], kh0,kh1);
                mma_bf16(d[0],d[1],d[2],d[3], qh4[0],qh4[1],qh4[2],qh4[3], kl0,kl1);
            }
        }

        // ---- scale + causal mask (in registers) ----
        bool diag = (k0 + 63 > q0);
        #pragma unroll
        for (int ni = 0; ni < 8; ni++) {
            int colb = k0 + ni*8 + tig*2;
            #pragma unroll
            for (int r = 0; r < 4; r++) {
                float sv = sacc[ni][r] * scale;
                if (diag && (colb + (r & 1) > rowg0 + ((r >> 1) ? 8 : 0))) sv = -1e30f;
                sacc[ni][r] = sv;
            }
        }

        // ---- register online softmax (rows rowg0, rowg0+8) ----
        {
            float m0 = -1e30f, m1 = -1e30f;
            #pragma unroll
            for (int ni = 0; ni < 8; ni++) {
                m0 = fmaxf(m0, fmaxf(sacc[ni][0], sacc[ni][1]));
                m1 = fmaxf(m1, fmaxf(sacc[ni][2], sacc[ni][3]));
            }
            m0 = fmaxf(m0, __shfl_xor_sync(0xffffffffu, m0, 1));
            m0 = fmaxf(m0, __shfl_xor_sync(0xffffffffu, m0, 2));
            m1 = fmaxf(m1, __shfl_xor_sync(0xffffffffu, m1, 1));
            m1 = fmaxf(m1, __shfl_xor_sync(0xffffffffu, m1, 2));
            float nm0 = fmaxf(rm0, m0), nm1 = fmaxf(rm1, m1);
            float f0 = __expf(rm0 - nm0), f1 = __expf(rm1 - nm1);
            rm0 = nm0; rm1 = nm1;
            float s0 = 0.0f, s1 = 0.0f;
            #pragma unroll
            for (int ni = 0; ni < 8; ni++) {
                sacc[ni][0] = __expf(sacc[ni][0] - nm0); s0 += sacc[ni][0];
                sacc[ni][1] = __expf(sacc[ni][1] - nm0); s0 += sacc[ni][1];
                sacc[ni][2] = __expf(sacc[ni][2] - nm1); s1 += sacc[ni][2];
                sacc[ni][3] = __expf(sacc[ni][3] - nm1); s1 += sacc[ni][3];
            }
            s0 += __shfl_xor_sync(0xffffffffu, s0, 1);
            s0 += __shfl_xor_sync(0xffffffffu, s0, 2);
            s1 += __shfl_xor_sync(0xffffffffu, s1, 1);
            s1 += __shfl_xor_sync(0xffffffffu, s1, 2);
            rl0 = rl0 * f0 + s0;
            rl1 = rl1 * f1 + s1;
            // rescale O
            #pragma unroll
            for (int ni = 0; ni < 16; ni++) {
                oacc[ni][0] *= f0; oacc[ni][1] *= f0;
                oacc[ni][2] *= f1; oacc[ni][3] *= f1;
            }
        }

        // ---- O += P @ V : warp tile 16 x 128 ; P repacked in-register ----
        #pragma unroll
        for (int ks = 0; ks < 4; ks++) {
            unsigned ph[4], pl[4];
            bsplit2(sacc[2*ks][0],   sacc[2*ks][1],   ph[0], pl[0]);
            bsplit2(sacc[2*ks][2],   sacc[2*ks][3],   ph[1], pl[1]);
            bsplit2(sacc[2*ks+1][0], sacc[2*ks+1][1], ph[2], pl[2]);
            bsplit2(sacc[2*ks+1][2], sacc[2*ks+1][3], ph[3], pl[3]);
            uint32_t kwB = (uint32_t)(ks * 32);
            #pragma unroll
            for (int ni = 0; ni < 16; ni++) {
                uint32_t ba = vBase + vLane + kwB + (uint32_t)(ni * 1152);
                unsigned vh0, vh1, vl0, vl1;
                ldsm2(vh0, vh1, ba);
                ldsm2(vl0, vl1, ba + 18432);
                float* d = oacc[ni];
                mma_bf16(d[0],d[1],d[2],d[3], ph[0],ph[1],ph[2],ph[3], vh0,vh1);
                mma_bf16(d[0],d[1],d[2],d[3], pl[0],pl[1],pl[2],pl[3], vh0,vh1);
                mma_bf16(d[0],d[1],d[2],d[3], ph[0],ph[1],ph[2],ph[3], vl0,vl1);
            }
        }
    }

    // ---- epilogue: O/l, write pre-split into GEMM A buffers ----
    int b = bh >> 4;
    int h = bh & 15;
    unsigned* AhW = (unsigned*)g_Ah;
    unsigned* AlW = (unsigned*)g_Al;
    float i0 = 1.0f / rl0;
    float i1 = 1.0f / rl1;
    #pragma unroll
    for (int ni = 0; ni < 16; ni++) {
        int col = h*HDIM + ni*8 + tig*2;
        unsigned hh, ll;
        size_t w = ((size_t)(b*TT + rowg0)) * (DD/2) + (col >> 1);
        bsplit2(oacc[ni][0] * i0, oacc[ni][1] * i0, hh, ll);
        AhW[w] = hh; AlW[w] = ll;
        w = ((size_t)(b*TT + rowg0 + 8)) * (DD/2) + (col >> 1);
        bsplit2(oacc[ni][2] * i1, oacc[ni][3] * i1, hh, ll);
        AhW[w] = hh; AlW[w] = ll;
    }
}

// ---------------------------------------------------------------------------
extern "C" void kernel_launch(void* const* d_in, const int* in_sizes, int n_in,
                              void* d_out, int out_size) {
    (void)in_sizes; (void)n_in; (void)out_size;
    const float* x       = (const float*)d_in[0];
    const float* Wq      = (const float*)d_in[1];
    const float* bq      = (const float*)d_in[2];
    const float* Wk      = (const float*)d_in[3];
    const float* bk      = (const float*)d_in[4];
    // d_in[5]=Wvq, d_in[6]=bvq, d_in[7]=v_keys: dead (top_k over full axis)
    const float* v_embed = (const float*)d_in[8];
    const float* Wo      = (const float*)d_in[9];
    const float* bo      = (const float*)d_in[10];
    float* out = (float*)d_out;

    __nv_bfloat16 *ah, *al, *bh, *bl, *b2h, *b2l, *qh, *ql, *kh, *kl;
    cudaGetSymbolAddress((void**)&ah,  g_Ah);
    cudaGetSymbolAddress((void**)&al,  g_Al);
    cudaGetSymbolAddress((void**)&bh,  g_Bh);
    cudaGetSymbolAddress((void**)&bl,  g_Bl);
    cudaGetSymbolAddress((void**)&b2h, g_B2h);
    cudaGetSymbolAddress((void**)&b2l, g_B2l);
    cudaGetSymbolAddress((void**)&qh,  g_Qh);
    cudaGetSymbolAddress((void**)&ql,  g_Ql);
    cudaGetSymbolAddress((void**)&kh,  g_Kh);
    cudaGetSymbolAddress((void**)&kl,  g_Kl);

    cudaFuncSetAttribute(gemm_qk_kernel,
                         cudaFuncAttributeMaxDynamicSharedMemorySize, G2_SMEM);
    cudaFuncSetAttribute(gemm_out_kernel,
                         cudaFuncAttributeMaxDynamicSharedMemorySize, G2_SMEM);
    cudaFuncSetAttribute(flash_v3_kernel,
                         cudaFuncAttributeMaxDynamicSharedMemorySize, F3_END);

    // launches 1-5: elementwise prep (ncu -s 5 -c 1 will capture launch 6 = gemm_qk)
    compute_c_kernel<<<DD/256, 256>>>(v_embed);
    vt_split_kernel<<<dim3(HDIM/32, TT/64, BB*HH), 256>>>(x);
    split_kernel<<<(MROWS*DD)/1024, 256>>>(x, ah, al);
    split_kernel<<<(DD*DD)/1024, 256>>>(Wq, bh, bl);
    split_kernel<<<(DD*DD)/1024, 256>>>(Wk, b2h, b2l);

    // launch 6: fused Q+K projection
    gemm_qk_kernel<<<dim3(DD/128, MROWS/128, 2), 128, G2_SMEM>>>(
        ah, al,
        bh, bl, bq, (unsigned*)qh, (unsigned*)ql,
        b2h, b2l, bk, (unsigned*)kh, (unsigned*)kl);

    // launch 7: split Wo (independent of flash; Bh free after gemm_qk)
    split_kernel<<<(DD*DD)/1024, 256>>>(Wo, bh, bl);

    // launch 8: flash attention (writes pre-split O into g_Ah/g_Al)
    flash_v3_kernel<<<dim3(16, BB*HH), 256, F3_END>>>();

    // launch 9: output projection
    gemm_out_kernel<<<dim3(DD/128, MROWS/128), 128, G2_SMEM>>>(
        ah, al, bh, bl, bo, out);
}